// round 13
// baseline (speedup 1.0000x reference)
#include <cuda_runtime.h>
#include <cuda_fp16.h>
#include <mma.h>
#include <math.h>
#include <cstdint>

using namespace nvcuda;

// ---------------------------------------------------------------------------
// Problem constants (B=2, N=2048, E=1024, H=16, D=64, FF=4096)
// ---------------------------------------------------------------------------
#define T_TOK   4096
#define E_DIM   1024
#define H_NUM   16
#define D_HEAD  64
#define FF_DIM  4096
#define SEQ_N   2048
#define EPS_LN  1e-5f

// ---------------------------------------------------------------------------
// Scratch (__device__ globals; allocation-free rule)
// ---------------------------------------------------------------------------
__device__ __half g_a  [(size_t)T_TOK * E_DIM];
__device__ __half g_w  [(size_t)E_DIM * FF_DIM];
__device__ __half g_f  [(size_t)T_TOK * FF_DIM];
__device__ float  g_x1 [(size_t)T_TOK * E_DIM];
__device__ __half g_q  [(size_t)T_TOK * E_DIM];
__device__ __half g_k  [(size_t)T_TOK * E_DIM];
__device__ __half g_v  [(size_t)T_TOK * E_DIM];

// ---------------------------------------------------------------------------
// Helpers
// ---------------------------------------------------------------------------
__device__ __forceinline__ float warp_sum(float v) {
    #pragma unroll
    for (int o = 16; o > 0; o >>= 1) v += __shfl_xor_sync(0xffffffffu, v, o);
    return v;
}
__device__ __forceinline__ uint32_t smem_u32(const void* p) {
    uint32_t a;
    asm("{ .reg .u64 t; cvta.to.shared.u64 t, %1; cvt.u32.u64 %0, t; }" : "=r"(a) : "l"(p));
    return a;
}
__device__ __forceinline__ uint32_t h2_as_u32(__half2 h) {
    union { __half2 h; uint32_t u; } cvt;
    cvt.h = h;
    return cvt.u;
}
__device__ __forceinline__ void ldsm_x4(uint32_t r[4], uint32_t addr) {
    asm volatile("ldmatrix.sync.aligned.m8n8.x4.shared.b16 {%0,%1,%2,%3}, [%4];"
                 : "=r"(r[0]), "=r"(r[1]), "=r"(r[2]), "=r"(r[3]) : "r"(addr));
}
__device__ __forceinline__ void ldsm_x4_t(uint32_t r[4], uint32_t addr) {
    asm volatile("ldmatrix.sync.aligned.m8n8.x4.trans.shared.b16 {%0,%1,%2,%3}, [%4];"
                 : "=r"(r[0]), "=r"(r[1]), "=r"(r[2]), "=r"(r[3]) : "r"(addr));
}
__device__ __forceinline__ void mma16816(float d[4], const uint32_t a[4],
                                         const uint32_t b[2], const float c[4]) {
    asm volatile(
        "mma.sync.aligned.m16n8k16.row.col.f32.f16.f16.f32 "
        "{%0,%1,%2,%3}, {%4,%5,%6,%7}, {%8,%9}, {%10,%11,%12,%13};"
        : "=f"(d[0]), "=f"(d[1]), "=f"(d[2]), "=f"(d[3])
        : "r"(a[0]), "r"(a[1]), "r"(a[2]), "r"(a[3]),
          "r"(b[0]), "r"(b[1]),
          "f"(c[0]), "f"(c[1]), "f"(c[2]), "f"(c[3]));
}
__device__ __forceinline__ void cp_async16(uint32_t dst, const void* src) {
    asm volatile("cp.async.cg.shared.global [%0], [%1], 16;" :: "r"(dst), "l"(src));
}
#define CP_COMMIT() asm volatile("cp.async.commit_group;" ::: "memory")
#define CP_WAIT1()  asm volatile("cp.async.wait_group 1;"  ::: "memory")

// ---------------------------------------------------------------------------
// LayerNorm -> fp16
// ---------------------------------------------------------------------------
__global__ void ln_fp16_kernel(const float* __restrict__ x,
                               const float* __restrict__ gamma,
                               const float* __restrict__ beta,
                               __half* __restrict__ o16)
{
    const int row = blockIdx.x;
    const int tid = threadIdx.x;
    const int w   = tid >> 5;
    const int ln  = tid & 31;

    const float4 v = reinterpret_cast<const float4*>(x + (size_t)row * E_DIM)[tid];
    float s  = v.x + v.y + v.z + v.w;
    float sq = v.x * v.x + v.y * v.y + v.z * v.z + v.w * v.w;
    s  = warp_sum(s);
    sq = warp_sum(sq);

    __shared__ float red_s[8], red_q[8];
    __shared__ float s_mu, s_rs;
    if (ln == 0) { red_s[w] = s; red_q[w] = sq; }
    __syncthreads();
    if (w == 0) {
        float ts = (ln < 8) ? red_s[ln] : 0.f;
        float tq = (ln < 8) ? red_q[ln] : 0.f;
        ts = warp_sum(ts); tq = warp_sum(tq);
        if (ln == 0) {
            float mu  = ts * (1.0f / E_DIM);
            float var = tq * (1.0f / E_DIM) - mu * mu;
            s_mu = mu; s_rs = rsqrtf(var + EPS_LN);
        }
    }
    __syncthreads();
    const float mu = s_mu, rs = s_rs;

    const float4 g = reinterpret_cast<const float4*>(gamma)[tid];
    const float4 b = reinterpret_cast<const float4*>(beta)[tid];
    __half h4[4];
    h4[0] = __float2half_rn((v.x - mu) * rs * g.x + b.x);
    h4[1] = __float2half_rn((v.y - mu) * rs * g.y + b.y);
    h4[2] = __float2half_rn((v.z - mu) * rs * g.z + b.z);
    h4[3] = __float2half_rn((v.w - mu) * rs * g.w + b.w);
    *reinterpret_cast<uint2*>(o16 + (size_t)row * E_DIM + tid * 4) = *reinterpret_cast<uint2*>(h4);
}

// ---------------------------------------------------------------------------
// fp32 -> fp16 (weights)
// ---------------------------------------------------------------------------
__global__ void wconv_kernel(const float* __restrict__ src,
                             __half* __restrict__ dst, int n)
{
    const int i = (blockIdx.x * blockDim.x + threadIdx.x) * 4;
    if (i >= n) return;
    const float4 v = *reinterpret_cast<const float4*>(src + i);
    __half h4[4];
    h4[0] = __float2half_rn(v.x); h4[1] = __float2half_rn(v.y);
    h4[2] = __float2half_rn(v.z); h4[3] = __float2half_rn(v.w);
    *reinterpret_cast<uint2*>(dst + i) = *reinterpret_cast<uint2*>(h4);
}

// ---------------------------------------------------------------------------
// fp16 GEMM: CTA tile 128x256, 8 warps (warp tile 64x64), k-tile 32,
// 3-stage cp.async pipeline, fused epilogue (two 128-col halves via staging).
//   EPI 0: qkv (+bias, head-major fp16 scatter, q*0.125)
//   EPI 1: gelu(+bias) -> fp16 [M,N]
//   EPI 2: +bias +res  -> fp32 [M,N]
// ---------------------------------------------------------------------------
#define LDC 132
#define LDB 264                     // B smem row stride (halfs)
#define STG_A 10240                 // 128 x 40 halfs x 2B
#define STG_B 16896                 // 32 x 264 halfs x 2B
#define STG_SZ (STG_A + STG_B)      // 27136
#define GEMM_SMEM (3 * STG_SZ)      // 81408 (> 128*132*4 = 67584 epilogue staging)

template <int EPI>
__global__ void __launch_bounds__(256)
gemm_fp16(const __half* __restrict__ A, const __half* __restrict__ B,
          const float* __restrict__ bias, const float* __restrict__ res,
          float* __restrict__ outf,
          __half* __restrict__ o0, __half* __restrict__ o1, __half* __restrict__ o2,
          int N, int K)
{
    extern __shared__ __align__(16) char sm[];
    float* Cs = (float*)sm;   // [128][132] epilogue staging (aliases stages)

    const int tid = threadIdx.x;
    const int wid = tid >> 5;
    const int wm  = wid & 1;          // 2 warps in M (64 rows each)
    const int wn  = wid >> 1;         // 4 warps in N (64 cols each)
    const int m0  = blockIdx.y * 128;
    const int n0  = blockIdx.x * 256;

    // A: 128x32 halfs = 512 int4 (2/thread); B: 32x256 halfs = 1024 int4 (4/thread)
    const int ca0 = tid * 2;
    const int ar0 = ca0 >> 2,     ac0 = (ca0 & 3) * 8;
    const int ar1 = (ca0+1) >> 2, ac1 = ((ca0+1) & 3) * 8;
    const int cb0 = tid * 4;

    wmma::fragment<wmma::accumulator, 16, 16, 16, float> acc[4][4];
    #pragma unroll
    for (int i = 0; i < 4; ++i)
        #pragma unroll
        for (int j = 0; j < 4; ++j) wmma::fill_fragment(acc[i][j], 0.0f);

    const int nt = K >> 5;

    auto issue = [&](int ti, int s) {
        char* st = sm + s * STG_SZ;
        const int k0 = ti * 32;
        cp_async16(smem_u32(st + (ar0 * 40 + ac0) * 2),
                   A + (size_t)(m0 + ar0) * K + k0 + ac0);
        cp_async16(smem_u32(st + (ar1 * 40 + ac1) * 2),
                   A + (size_t)(m0 + ar1) * K + k0 + ac1);
        #pragma unroll
        for (int r = 0; r < 4; ++r) {
            const int cb = cb0 + r;
            const int brow = cb >> 5, bcol = (cb & 31) * 8;
            cp_async16(smem_u32(st + STG_A + (brow * LDB + bcol) * 2),
                       B + (size_t)(k0 + brow) * N + n0 + bcol);
        }
    };

    issue(0, 0); CP_COMMIT();
    if (nt > 1) issue(1, 1);
    CP_COMMIT();

    int s = 0;
    for (int ti = 0; ti < nt; ++ti) {
        CP_WAIT1();
        __syncthreads();

        const __half* As = (const __half*)(sm + s * STG_SZ);
        const __half* Bs = (const __half*)(sm + s * STG_SZ + STG_A);

        #pragma unroll
        for (int kk = 0; kk < 2; ++kk) {
            wmma::fragment<wmma::matrix_a, 16, 16, 16, __half, wmma::row_major> af[4];
            wmma::fragment<wmma::matrix_b, 16, 16, 16, __half, wmma::row_major> bf[4];
            #pragma unroll
            for (int i = 0; i < 4; ++i)
                wmma::load_matrix_sync(af[i], As + (wm * 64 + i * 16) * 40 + kk * 16, 40);
            #pragma unroll
            for (int j = 0; j < 4; ++j)
                wmma::load_matrix_sync(bf[j], Bs + (kk * 16) * LDB + wn * 64 + j * 16, LDB);
            #pragma unroll
            for (int i = 0; i < 4; ++i)
                #pragma unroll
                for (int j = 0; j < 4; ++j)
                    wmma::mma_sync(acc[i][j], af[i], bf[j], acc[i][j]);
        }

        if (ti + 2 < nt) issue(ti + 2, (ti + 2) % 3);
        CP_COMMIT();

        s = (s + 1 == 3) ? 0 : s + 1;
    }
    __syncthreads();

    // ---- epilogue in two 128-column halves (staging buffer [128][132] fp32)
    #pragma unroll
    for (int half = 0; half < 2; ++half) {
        // warps with wn in {2h, 2h+1} own this half's columns
        if ((wn >> 1) == half) {
            #pragma unroll
            for (int i = 0; i < 4; ++i)
                #pragma unroll
                for (int j = 0; j < 4; ++j)
                    wmma::store_matrix_sync(
                        Cs + (wm * 64 + i * 16) * LDC + (wn & 1) * 64 + j * 16,
                        acc[i][j], LDC, wmma::mem_row_major);
        }
        __syncthreads();

        const int r   = tid >> 1;
        const int ch  = (tid & 1) * 64;
        const int row = m0 + r;
        const int c0  = n0 + half * 128 + ch;
        const float* cr = Cs + r * LDC + ch;

        if (EPI == 0) {
            const int sss = c0 >> 10;
            const int hh  = (c0 & 1023) >> 6;
            const float sc = (sss == 0) ? 0.125f : 1.0f;
            const int bb = row >> 11, nn = row & 2047;
            __half* dst = ((sss == 0) ? o0 : (sss == 1) ? o1 : o2)
                        + (((size_t)(bb * H_NUM + hh)) * SEQ_N + nn) * D_HEAD;
            #pragma unroll
            for (int j = 0; j < 64; j += 8) {
                __half h8[8];
                #pragma unroll
                for (int q = 0; q < 8; ++q)
                    h8[q] = __float2half_rn((cr[j + q] + bias[c0 + j + q]) * sc);
                *reinterpret_cast<uint4*>(dst + j) = *reinterpret_cast<uint4*>(h8);
            }
        } else if (EPI == 1) {
            __half* dst = o0 + (size_t)row * N + c0;
            #pragma unroll
            for (int j = 0; j < 64; j += 8) {
                __half h8[8];
                #pragma unroll
                for (int q = 0; q < 8; ++q) {
                    const float v = cr[j + q] + bias[c0 + j + q];
                    h8[q] = __float2half_rn(0.5f * v * (1.0f + erff(v * 0.70710678118654752f)));
                }
                *reinterpret_cast<uint4*>(dst + j) = *reinterpret_cast<uint4*>(h8);
            }
        } else {
            const float* rp = res + (size_t)row * N + c0;
            float* op = outf + (size_t)row * N + c0;
            #pragma unroll
            for (int j = 0; j < 64; j += 4) {
                const float4 b4 = *reinterpret_cast<const float4*>(bias + c0 + j);
                const float4 r4 = *reinterpret_cast<const float4*>(rp + j);
                float4 o;
                o.x = cr[j + 0] + b4.x + r4.x;
                o.y = cr[j + 1] + b4.y + r4.y;
                o.z = cr[j + 2] + b4.z + r4.z;
                o.w = cr[j + 3] + b4.w + r4.w;
                *reinterpret_cast<float4*>(op + j) = o;
            }
        }
        __syncthreads();
    }
}

// ---------------------------------------------------------------------------
// Flash attention, register-resident (R10 config: QT=64, 128 thr, sync loads).
// ---------------------------------------------------------------------------
#define QT   64
#define KTT  64
#define LDAH 72

__global__ void __launch_bounds__(128)
attn_mma(const __half* __restrict__ q_g, const __half* __restrict__ k_g,
         const __half* __restrict__ v_g, __half* __restrict__ o_g)
{
    __shared__ __half Qs[QT * LDAH];
    __shared__ __half Ks[KTT * LDAH];
    __shared__ __half Vs[KTT * LDAH];

    const int tid  = threadIdx.x;
    const int lane = tid & 31;
    const int wid  = tid >> 5;
    const int bh   = blockIdx.y;
    const int n0   = blockIdx.x * QT;

    {
        const int4* qp = (const int4*)(q_g + ((size_t)bh * SEQ_N + n0) * D_HEAD);
        #pragma unroll
        for (int i = 0; i < 4; ++i) {
            const int idx = tid + i * 128;
            *(int4*)(Qs + (idx >> 3) * LDAH + (idx & 7) * 8) = qp[idx];
        }
    }
    __syncthreads();

    const uint32_t qsm = smem_u32(Qs);
    uint32_t qa[4][4];
    {
        const int rq = wid * 16 + (lane & 15);
        #pragma unroll
        for (int c = 0; c < 4; ++c) {
            const uint32_t addr = qsm + (rq * LDAH + c * 16 + ((lane >> 4) << 3)) * 2;
            ldsm_x4(qa[c], addr);
        }
    }

    const uint32_t ksm = smem_u32(Ks);
    const uint32_t vsm = smem_u32(Vs);

    float of[8][4];
    #pragma unroll
    for (int f = 0; f < 8; ++f)
        #pragma unroll
        for (int q = 0; q < 4; ++q) of[f][q] = 0.f;
    float m0v = -1e30f, m1v = -1e30f, l0 = 0.f, l1 = 0.f;

    for (int j0 = 0; j0 < SEQ_N; j0 += KTT) {
        __syncthreads();
        {
            const int4* kp = (const int4*)(k_g + ((size_t)bh * SEQ_N + j0) * D_HEAD);
            const int4* vp = (const int4*)(v_g + ((size_t)bh * SEQ_N + j0) * D_HEAD);
            #pragma unroll
            for (int i = 0; i < 4; ++i) {
                const int idx = tid + i * 128;
                const int off = (idx >> 3) * LDAH + (idx & 7) * 8;
                *(int4*)(Ks + off) = kp[idx];
                *(int4*)(Vs + off) = vp[idx];
            }
        }
        __syncthreads();

        float sf[8][4];
        #pragma unroll
        for (int f = 0; f < 8; ++f)
            #pragma unroll
            for (int q = 0; q < 4; ++q) sf[f][q] = 0.f;

        #pragma unroll
        for (int f = 0; f < 4; ++f) {
            #pragma unroll
            for (int kk = 0; kk < 4; ++kk) {
                uint32_t b4[4];
                const uint32_t addr = ksm +
                    ((f * 16 + (lane & 7) + ((lane >> 4) << 3)) * LDAH
                     + kk * 16 + (lane & 8)) * 2;
                ldsm_x4(b4, addr);
                mma16816(sf[2 * f],     qa[kk], b4,     sf[2 * f]);
                mma16816(sf[2 * f + 1], qa[kk], b4 + 2, sf[2 * f + 1]);
            }
        }

        float mx0 = -1e30f, mx1 = -1e30f;
        #pragma unroll
        for (int f = 0; f < 8; ++f) {
            mx0 = fmaxf(mx0, fmaxf(sf[f][0], sf[f][1]));
            mx1 = fmaxf(mx1, fmaxf(sf[f][2], sf[f][3]));
        }
        mx0 = fmaxf(mx0, __shfl_xor_sync(0xffffffffu, mx0, 1));
        mx0 = fmaxf(mx0, __shfl_xor_sync(0xffffffffu, mx0, 2));
        mx1 = fmaxf(mx1, __shfl_xor_sync(0xffffffffu, mx1, 1));
        mx1 = fmaxf(mx1, __shfl_xor_sync(0xffffffffu, mx1, 2));

        const float nm0 = fmaxf(m0v, mx0);
        const float nm1 = fmaxf(m1v, mx1);
        const float a0  = __expf(m0v - nm0);
        const float a1  = __expf(m1v - nm1);

        float s0 = 0.f, s1 = 0.f;
        #pragma unroll
        for (int f = 0; f < 8; ++f) {
            sf[f][0] = __expf(sf[f][0] - nm0);
            sf[f][1] = __expf(sf[f][1] - nm0);
            sf[f][2] = __expf(sf[f][2] - nm1);
            sf[f][3] = __expf(sf[f][3] - nm1);
            s0 += sf[f][0] + sf[f][1];
            s1 += sf[f][2] + sf[f][3];
        }
        s0 += __shfl_xor_sync(0xffffffffu, s0, 1);
        s0 += __shfl_xor_sync(0xffffffffu, s0, 2);
        s1 += __shfl_xor_sync(0xffffffffu, s1, 1);
        s1 += __shfl_xor_sync(0xffffffffu, s1, 2);

        l0 = l0 * a0 + s0;
        l1 = l1 * a1 + s1;
        m0v = nm0; m1v = nm1;

        #pragma unroll
        for (int f = 0; f < 8; ++f) {
            of[f][0] *= a0; of[f][1] *= a0;
            of[f][2] *= a1; of[f][3] *= a1;
        }

        uint32_t pa[4][4];
        #pragma unroll
        for (int c = 0; c < 4; ++c) {
            pa[c][0] = h2_as_u32(__floats2half2_rn(sf[2*c][0],   sf[2*c][1]));
            pa[c][1] = h2_as_u32(__floats2half2_rn(sf[2*c][2],   sf[2*c][3]));
            pa[c][2] = h2_as_u32(__floats2half2_rn(sf[2*c+1][0], sf[2*c+1][1]));
            pa[c][3] = h2_as_u32(__floats2half2_rn(sf[2*c+1][2], sf[2*c+1][3]));
        }

        #pragma unroll
        for (int f = 0; f < 4; ++f) {
            #pragma unroll
            for (int kk = 0; kk < 4; ++kk) {
                uint32_t b4[4];
                const uint32_t addr = vsm +
                    ((kk * 16 + (lane & 15)) * LDAH
                     + f * 16 + ((lane >> 4) << 3)) * 2;
                ldsm_x4_t(b4, addr);
                mma16816(of[2 * f],     pa[kk], b4,     of[2 * f]);
                mma16816(of[2 * f + 1], pa[kk], b4 + 2, of[2 * f + 1]);
            }
        }
    }

    {
        const float inv0 = 1.0f / l0;
        const float inv1 = 1.0f / l1;
        const int b = bh >> 4, h = bh & 15;
        const int r0 = n0 + wid * 16 + (lane >> 2);
        const int r1 = r0 + 8;
        const size_t base0 = ((size_t)(b * SEQ_N) + r0) * E_DIM + h * D_HEAD + (lane & 3) * 2;
        const size_t base1 = ((size_t)(b * SEQ_N) + r1) * E_DIM + h * D_HEAD + (lane & 3) * 2;
        #pragma unroll
        for (int f = 0; f < 8; ++f) {
            *(__half2*)(o_g + base0 + f * 8) = __floats2half2_rn(of[f][0] * inv0, of[f][1] * inv0);
            *(__half2*)(o_g + base1 + f * 8) = __floats2half2_rn(of[f][2] * inv1, of[f][3] * inv1);
        }
    }
}

// ---------------------------------------------------------------------------
// Launch
// ---------------------------------------------------------------------------
static float* sym_addr_f(const void* symbol)
{
    void* p = nullptr;
    cudaGetSymbolAddress(&p, symbol);
    return reinterpret_cast<float*>(p);
}
static __half* sym_addr_h(const void* symbol)
{
    void* p = nullptr;
    cudaGetSymbolAddress(&p, symbol);
    return reinterpret_cast<__half*>(p);
}

extern "C" void kernel_launch(void* const* d_in, const int* in_sizes, int n_in,
                              void* d_out, int out_size)
{
    const float* x      = (const float*)d_in[0];
    const float* ln1_g  = (const float*)d_in[1];
    const float* ln1_b  = (const float*)d_in[2];
    const float* qkv_w  = (const float*)d_in[3];
    const float* qkv_b  = (const float*)d_in[4];
    const float* proj_w = (const float*)d_in[5];
    const float* proj_b = (const float*)d_in[6];
    const float* ln2_g  = (const float*)d_in[7];
    const float* ln2_b  = (const float*)d_in[8];
    const float* fc1_w  = (const float*)d_in[9];
    const float* fc1_b  = (const float*)d_in[10];
    const float* fc2_w  = (const float*)d_in[11];
    const float* fc2_b  = (const float*)d_in[12];
    float* out = (float*)d_out;

    __half* a  = sym_addr_h(g_a);
    __half* w  = sym_addr_h(g_w);
    __half* f  = sym_addr_h(g_f);
    float* x1  = sym_addr_f(g_x1);
    __half* qq = sym_addr_h(g_q);
    __half* kk = sym_addr_h(g_k);
    __half* vv = sym_addr_h(g_v);

    cudaFuncSetAttribute(gemm_fp16<0>, cudaFuncAttributeMaxDynamicSharedMemorySize, GEMM_SMEM);
    cudaFuncSetAttribute(gemm_fp16<1>, cudaFuncAttributeMaxDynamicSharedMemorySize, GEMM_SMEM);
    cudaFuncSetAttribute(gemm_fp16<2>, cudaFuncAttributeMaxDynamicSharedMemorySize, GEMM_SMEM);

    const int n_qkvw  = E_DIM * 3 * E_DIM;
    const int n_projw = E_DIM * E_DIM;
    const int n_fc1w  = E_DIM * FF_DIM;
    const int n_fc2w  = FF_DIM * E_DIM;

    // 1) h = LN1(x) -> fp16
    ln_fp16_kernel<<<T_TOK, 256>>>(x, ln1_g, ln1_b, a);

    // 2) qkv = h @ qkv_w + qkv_b -> head-major q/k/v (fused epilogue)
    wconv_kernel<<<n_qkvw / 1024, 256>>>(qkv_w, w, n_qkvw);
    gemm_fp16<0><<<dim3(3 * E_DIM / 256, T_TOK / 128), 256, GEMM_SMEM>>>(
        a, w, qkv_b, nullptr, nullptr, qq, kk, vv, 3 * E_DIM, E_DIM);

    // 3) attention (register-resident flash)
    attn_mma<<<dim3(SEQ_N / QT, 2 * H_NUM), 128>>>(qq, kk, vv, a);

    // 4) x1 = x + attn @ proj_w + proj_b (fused)
    wconv_kernel<<<n_projw / 1024, 256>>>(proj_w, w, n_projw);
    gemm_fp16<2><<<dim3(E_DIM / 256, T_TOK / 128), 256, GEMM_SMEM>>>(
        a, w, proj_b, x, x1, nullptr, nullptr, nullptr, E_DIM, E_DIM);

    // 5) h = LN2(x1) -> fp16
    ln_fp16_kernel<<<T_TOK, 256>>>(x1, ln2_g, ln2_b, a);

    // 6) ff = gelu(h @ fc1_w + fc1_b) -> fp16 (fused)
    wconv_kernel<<<n_fc1w / 1024, 256>>>(fc1_w, w, n_fc1w);
    gemm_fp16<1><<<dim3(FF_DIM / 256, T_TOK / 128), 256, GEMM_SMEM>>>(
        a, w, fc1_b, nullptr, nullptr, f, nullptr, nullptr, FF_DIM, E_DIM);

    // 7) out = x1 + ff @ fc2_w + fc2_b (fused)
    wconv_kernel<<<n_fc2w / 1024, 256>>>(fc2_w, w, n_fc2w);
    gemm_fp16<2><<<dim3(E_DIM / 256, T_TOK / 128), 256, GEMM_SMEM>>>(
        f, w, fc2_b, x1, out, nullptr, nullptr, nullptr, E_DIM, FF_DIM);
}

// round 14
// speedup vs baseline: 1.2151x; 1.2151x over previous
#include <cuda_runtime.h>
#include <cuda_fp16.h>
#include <mma.h>
#include <math.h>
#include <cstdint>

using namespace nvcuda;

// ---------------------------------------------------------------------------
// Problem constants (B=2, N=2048, E=1024, H=16, D=64, FF=4096)
// ---------------------------------------------------------------------------
#define T_TOK   4096
#define E_DIM   1024
#define H_NUM   16
#define D_HEAD  64
#define FF_DIM  4096
#define SEQ_N   2048
#define EPS_LN  1e-5f

// ---------------------------------------------------------------------------
// Scratch (__device__ globals; allocation-free rule)
// ---------------------------------------------------------------------------
__device__ __half g_a  [(size_t)T_TOK * E_DIM];
__device__ __half g_w  [(size_t)E_DIM * FF_DIM];
__device__ __half g_f  [(size_t)T_TOK * FF_DIM];
__device__ float  g_x1 [(size_t)T_TOK * E_DIM];
__device__ __half g_q  [(size_t)T_TOK * E_DIM];
__device__ __half g_k  [(size_t)T_TOK * E_DIM];
__device__ __half g_v  [(size_t)T_TOK * E_DIM];

// ---------------------------------------------------------------------------
// Helpers
// ---------------------------------------------------------------------------
__device__ __forceinline__ float warp_sum(float v) {
    #pragma unroll
    for (int o = 16; o > 0; o >>= 1) v += __shfl_xor_sync(0xffffffffu, v, o);
    return v;
}
__device__ __forceinline__ uint32_t smem_u32(const void* p) {
    uint32_t a;
    asm("{ .reg .u64 t; cvta.to.shared.u64 t, %1; cvt.u32.u64 %0, t; }" : "=r"(a) : "l"(p));
    return a;
}
__device__ __forceinline__ uint32_t h2_as_u32(__half2 h) {
    union { __half2 h; uint32_t u; } cvt;
    cvt.h = h;
    return cvt.u;
}
__device__ __forceinline__ void ldsm_x4(uint32_t r[4], uint32_t addr) {
    asm volatile("ldmatrix.sync.aligned.m8n8.x4.shared.b16 {%0,%1,%2,%3}, [%4];"
                 : "=r"(r[0]), "=r"(r[1]), "=r"(r[2]), "=r"(r[3]) : "r"(addr));
}
__device__ __forceinline__ void ldsm_x4_t(uint32_t r[4], uint32_t addr) {
    asm volatile("ldmatrix.sync.aligned.m8n8.x4.trans.shared.b16 {%0,%1,%2,%3}, [%4];"
                 : "=r"(r[0]), "=r"(r[1]), "=r"(r[2]), "=r"(r[3]) : "r"(addr));
}
__device__ __forceinline__ void mma16816(float d[4], const uint32_t a[4],
                                         const uint32_t b[2], const float c[4]) {
    asm volatile(
        "mma.sync.aligned.m16n8k16.row.col.f32.f16.f16.f32 "
        "{%0,%1,%2,%3}, {%4,%5,%6,%7}, {%8,%9}, {%10,%11,%12,%13};"
        : "=f"(d[0]), "=f"(d[1]), "=f"(d[2]), "=f"(d[3])
        : "r"(a[0]), "r"(a[1]), "r"(a[2]), "r"(a[3]),
          "r"(b[0]), "r"(b[1]),
          "f"(c[0]), "f"(c[1]), "f"(c[2]), "f"(c[3]));
}
__device__ __forceinline__ void cp_async16(uint32_t dst, const void* src) {
    asm volatile("cp.async.cg.shared.global [%0], [%1], 16;" :: "r"(dst), "l"(src));
}
#define CP_COMMIT() asm volatile("cp.async.commit_group;" ::: "memory")
#define CP_WAIT2()  asm volatile("cp.async.wait_group 2;"  ::: "memory")

// ---------------------------------------------------------------------------
// LayerNorm -> fp16
// ---------------------------------------------------------------------------
__global__ void ln_fp16_kernel(const float* __restrict__ x,
                               const float* __restrict__ gamma,
                               const float* __restrict__ beta,
                               __half* __restrict__ o16)
{
    const int row = blockIdx.x;
    const int tid = threadIdx.x;
    const int w   = tid >> 5;
    const int ln  = tid & 31;

    const float4 v = reinterpret_cast<const float4*>(x + (size_t)row * E_DIM)[tid];
    float s  = v.x + v.y + v.z + v.w;
    float sq = v.x * v.x + v.y * v.y + v.z * v.z + v.w * v.w;
    s  = warp_sum(s);
    sq = warp_sum(sq);

    __shared__ float red_s[8], red_q[8];
    __shared__ float s_mu, s_rs;
    if (ln == 0) { red_s[w] = s; red_q[w] = sq; }
    __syncthreads();
    if (w == 0) {
        float ts = (ln < 8) ? red_s[ln] : 0.f;
        float tq = (ln < 8) ? red_q[ln] : 0.f;
        ts = warp_sum(ts); tq = warp_sum(tq);
        if (ln == 0) {
            float mu  = ts * (1.0f / E_DIM);
            float var = tq * (1.0f / E_DIM) - mu * mu;
            s_mu = mu; s_rs = rsqrtf(var + EPS_LN);
        }
    }
    __syncthreads();
    const float mu = s_mu, rs = s_rs;

    const float4 g = reinterpret_cast<const float4*>(gamma)[tid];
    const float4 b = reinterpret_cast<const float4*>(beta)[tid];
    __half h4[4];
    h4[0] = __float2half_rn((v.x - mu) * rs * g.x + b.x);
    h4[1] = __float2half_rn((v.y - mu) * rs * g.y + b.y);
    h4[2] = __float2half_rn((v.z - mu) * rs * g.z + b.z);
    h4[3] = __float2half_rn((v.w - mu) * rs * g.w + b.w);
    *reinterpret_cast<uint2*>(o16 + (size_t)row * E_DIM + tid * 4) = *reinterpret_cast<uint2*>(h4);
}

// ---------------------------------------------------------------------------
// fp32 -> fp16 (weights)
// ---------------------------------------------------------------------------
__global__ void wconv_kernel(const float* __restrict__ src,
                             __half* __restrict__ dst, int n)
{
    const int i = (blockIdx.x * blockDim.x + threadIdx.x) * 4;
    if (i >= n) return;
    const float4 v = *reinterpret_cast<const float4*>(src + i);
    __half h4[4];
    h4[0] = __float2half_rn(v.x); h4[1] = __float2half_rn(v.y);
    h4[2] = __float2half_rn(v.z); h4[3] = __float2half_rn(v.w);
    *reinterpret_cast<uint2*>(dst + i) = *reinterpret_cast<uint2*>(h4);
}

// ---------------------------------------------------------------------------
// fp16 GEMM (wmma m16n16k16), 128x128 block, 8 warps (64x32 warp tile),
// k-tile 32, 4-stage cp.async pipeline, FUSED epilogue via fp32 smem staging.
// (R12's measured-best GEMM)
// ---------------------------------------------------------------------------
#define LDC 132
#define STG_A 10240               // 128 rows x 40 halfs x 2B
#define STG_B 8704                // 32 rows x 136 halfs x 2B
#define STG_SZ (STG_A + STG_B)    // 18944
#define N_STAGES 4
#define GEMM_SMEM (N_STAGES * STG_SZ > 128 * LDC * 4 ? N_STAGES * STG_SZ : 128 * LDC * 4)

template <int EPI>
__global__ void __launch_bounds__(256)
gemm_fp16(const __half* __restrict__ A, const __half* __restrict__ B,
          const float* __restrict__ bias, const float* __restrict__ res,
          float* __restrict__ outf,
          __half* __restrict__ o0, __half* __restrict__ o1, __half* __restrict__ o2,
          int N, int K)
{
    extern __shared__ __align__(16) char sm[];
    float* Cs = (float*)sm;   // [128][132] epilogue staging (aliases stages)

    const int tid = threadIdx.x;
    const int wid = tid >> 5;
    const int wm  = wid & 1;
    const int wn  = wid >> 1;
    const int m0  = blockIdx.y * 128;
    const int n0  = blockIdx.x * 128;

    const int ca0 = tid * 2;
    const int ar0 = ca0 >> 2,  ac0 = (ca0 & 3) * 8;
    const int ar1 = (ca0+1) >> 2, ac1 = ((ca0+1) & 3) * 8;
    const int br0 = ca0 >> 4,  bc0 = (ca0 & 15) * 8;
    const int br1 = (ca0+1) >> 4, bc1 = ((ca0+1) & 15) * 8;

    wmma::fragment<wmma::accumulator, 16, 16, 16, float> acc[4][2];
    #pragma unroll
    for (int i = 0; i < 4; ++i)
        #pragma unroll
        for (int j = 0; j < 2; ++j) wmma::fill_fragment(acc[i][j], 0.0f);

    const int nt = K >> 5;

    auto issue = [&](int ti, int s) {
        char* st = sm + s * STG_SZ;
        const int k0 = ti * 32;
        cp_async16(smem_u32(st + (ar0 * 40 + ac0) * 2),
                   A + (size_t)(m0 + ar0) * K + k0 + ac0);
        cp_async16(smem_u32(st + (ar1 * 40 + ac1) * 2),
                   A + (size_t)(m0 + ar1) * K + k0 + ac1);
        cp_async16(smem_u32(st + STG_A + (br0 * 136 + bc0) * 2),
                   B + (size_t)(k0 + br0) * N + n0 + bc0);
        cp_async16(smem_u32(st + STG_A + (br1 * 136 + bc1) * 2),
                   B + (size_t)(k0 + br1) * N + n0 + bc1);
    };

    issue(0, 0); CP_COMMIT();
    if (nt > 1) issue(1, 1);
    CP_COMMIT();
    if (nt > 2) issue(2, 2);
    CP_COMMIT();

    int s = 0;
    for (int ti = 0; ti < nt; ++ti) {
        CP_WAIT2();
        __syncthreads();

        const __half* As = (const __half*)(sm + s * STG_SZ);
        const __half* Bs = (const __half*)(sm + s * STG_SZ + STG_A);

        #pragma unroll
        for (int kk = 0; kk < 2; ++kk) {
            wmma::fragment<wmma::matrix_a, 16, 16, 16, __half, wmma::row_major> af[4];
            wmma::fragment<wmma::matrix_b, 16, 16, 16, __half, wmma::row_major> bf[2];
            #pragma unroll
            for (int i = 0; i < 4; ++i)
                wmma::load_matrix_sync(af[i], As + (wm * 64 + i * 16) * 40 + kk * 16, 40);
            #pragma unroll
            for (int j = 0; j < 2; ++j)
                wmma::load_matrix_sync(bf[j], Bs + (kk * 16) * 136 + wn * 32 + j * 16, 136);
            #pragma unroll
            for (int i = 0; i < 4; ++i)
                #pragma unroll
                for (int j = 0; j < 2; ++j)
                    wmma::mma_sync(acc[i][j], af[i], bf[j], acc[i][j]);
        }

        if (ti + 3 < nt) issue(ti + 3, (ti + 3) & 3);
        CP_COMMIT();

        s = (s + 1) & 3;
    }
    __syncthreads();

    #pragma unroll
    for (int i = 0; i < 4; ++i)
        #pragma unroll
        for (int j = 0; j < 2; ++j)
            wmma::store_matrix_sync(Cs + (wm * 64 + i * 16) * LDC + wn * 32 + j * 16,
                                    acc[i][j], LDC, wmma::mem_row_major);
    __syncthreads();

    {
        const int r   = tid >> 1;
        const int ch  = (tid & 1) * 64;
        const int row = m0 + r;
        const int c0  = n0 + ch;
        const float* cr = Cs + r * LDC + ch;

        if (EPI == 0) {
            const int sss = c0 >> 10;
            const int hh  = (c0 & 1023) >> 6;
            const float sc = (sss == 0) ? 0.125f : 1.0f;
            const int bb = row >> 11, nn = row & 2047;
            __half* dst = ((sss == 0) ? o0 : (sss == 1) ? o1 : o2)
                        + (((size_t)(bb * H_NUM + hh)) * SEQ_N + nn) * D_HEAD;
            #pragma unroll
            for (int j = 0; j < 64; j += 8) {
                __half h8[8];
                #pragma unroll
                for (int q = 0; q < 8; ++q)
                    h8[q] = __float2half_rn((cr[j + q] + bias[c0 + j + q]) * sc);
                *reinterpret_cast<uint4*>(dst + j) = *reinterpret_cast<uint4*>(h8);
            }
        } else if (EPI == 1) {
            __half* dst = o0 + (size_t)row * N + c0;
            #pragma unroll
            for (int j = 0; j < 64; j += 8) {
                __half h8[8];
                #pragma unroll
                for (int q = 0; q < 8; ++q) {
                    const float v = cr[j + q] + bias[c0 + j + q];
                    h8[q] = __float2half_rn(0.5f * v * (1.0f + erff(v * 0.70710678118654752f)));
                }
                *reinterpret_cast<uint4*>(dst + j) = *reinterpret_cast<uint4*>(h8);
            }
        } else {
            const float* rp = res + (size_t)row * N + c0;
            float* op = outf + (size_t)row * N + c0;
            #pragma unroll
            for (int j = 0; j < 64; j += 4) {
                const float4 b4 = *reinterpret_cast<const float4*>(bias + c0 + j);
                const float4 r4 = *reinterpret_cast<const float4*>(rp + j);
                float4 o;
                o.x = cr[j + 0] + b4.x + r4.x;
                o.y = cr[j + 1] + b4.y + r4.y;
                o.z = cr[j + 2] + b4.z + r4.z;
                o.w = cr[j + 3] + b4.w + r4.w;
                *reinterpret_cast<float4*>(op + j) = o;
            }
        }
    }
}

// ---------------------------------------------------------------------------
// Flash attention, register-resident (QT=64, 128 thr; R10/R13 measured-best).
// ---------------------------------------------------------------------------
#define QT   64
#define KTT  64
#define LDAH 72

__global__ void __launch_bounds__(128)
attn_mma(const __half* __restrict__ q_g, const __half* __restrict__ k_g,
         const __half* __restrict__ v_g, __half* __restrict__ o_g)
{
    __shared__ __half Qs[QT * LDAH];
    __shared__ __half Ks[KTT * LDAH];
    __shared__ __half Vs[KTT * LDAH];

    const int tid  = threadIdx.x;
    const int lane = tid & 31;
    const int wid  = tid >> 5;
    const int bh   = blockIdx.y;
    const int n0   = blockIdx.x * QT;

    {
        const int4* qp = (const int4*)(q_g + ((size_t)bh * SEQ_N + n0) * D_HEAD);
        #pragma unroll
        for (int i = 0; i < 4; ++i) {
            const int idx = tid + i * 128;
            *(int4*)(Qs + (idx >> 3) * LDAH + (idx & 7) * 8) = qp[idx];
        }
    }
    __syncthreads();

    const uint32_t qsm = smem_u32(Qs);
    uint32_t qa[4][4];
    {
        const int rq = wid * 16 + (lane & 15);
        #pragma unroll
        for (int c = 0; c < 4; ++c) {
            const uint32_t addr = qsm + (rq * LDAH + c * 16 + ((lane >> 4) << 3)) * 2;
            ldsm_x4(qa[c], addr);
        }
    }

    const uint32_t ksm = smem_u32(Ks);
    const uint32_t vsm = smem_u32(Vs);

    float of[8][4];
    #pragma unroll
    for (int f = 0; f < 8; ++f)
        #pragma unroll
        for (int q = 0; q < 4; ++q) of[f][q] = 0.f;
    float m0v = -1e30f, m1v = -1e30f, l0 = 0.f, l1 = 0.f;

    for (int j0 = 0; j0 < SEQ_N; j0 += KTT) {
        __syncthreads();
        {
            const int4* kp = (const int4*)(k_g + ((size_t)bh * SEQ_N + j0) * D_HEAD);
            const int4* vp = (const int4*)(v_g + ((size_t)bh * SEQ_N + j0) * D_HEAD);
            #pragma unroll
            for (int i = 0; i < 4; ++i) {
                const int idx = tid + i * 128;
                const int off = (idx >> 3) * LDAH + (idx & 7) * 8;
                *(int4*)(Ks + off) = kp[idx];
                *(int4*)(Vs + off) = vp[idx];
            }
        }
        __syncthreads();

        float sf[8][4];
        #pragma unroll
        for (int f = 0; f < 8; ++f)
            #pragma unroll
            for (int q = 0; q < 4; ++q) sf[f][q] = 0.f;

        #pragma unroll
        for (int f = 0; f < 4; ++f) {
            #pragma unroll
            for (int kk = 0; kk < 4; ++kk) {
                uint32_t b4[4];
                const uint32_t addr = ksm +
                    ((f * 16 + (lane & 7) + ((lane >> 4) << 3)) * LDAH
                     + kk * 16 + (lane & 8)) * 2;
                ldsm_x4(b4, addr);
                mma16816(sf[2 * f],     qa[kk], b4,     sf[2 * f]);
                mma16816(sf[2 * f + 1], qa[kk], b4 + 2, sf[2 * f + 1]);
            }
        }

        float mx0 = -1e30f, mx1 = -1e30f;
        #pragma unroll
        for (int f = 0; f < 8; ++f) {
            mx0 = fmaxf(mx0, fmaxf(sf[f][0], sf[f][1]));
            mx1 = fmaxf(mx1, fmaxf(sf[f][2], sf[f][3]));
        }
        mx0 = fmaxf(mx0, __shfl_xor_sync(0xffffffffu, mx0, 1));
        mx0 = fmaxf(mx0, __shfl_xor_sync(0xffffffffu, mx0, 2));
        mx1 = fmaxf(mx1, __shfl_xor_sync(0xffffffffu, mx1, 1));
        mx1 = fmaxf(mx1, __shfl_xor_sync(0xffffffffu, mx1, 2));

        const float nm0 = fmaxf(m0v, mx0);
        const float nm1 = fmaxf(m1v, mx1);
        const float a0  = __expf(m0v - nm0);
        const float a1  = __expf(m1v - nm1);

        float s0 = 0.f, s1 = 0.f;
        #pragma unroll
        for (int f = 0; f < 8; ++f) {
            sf[f][0] = __expf(sf[f][0] - nm0);
            sf[f][1] = __expf(sf[f][1] - nm0);
            sf[f][2] = __expf(sf[f][2] - nm1);
            sf[f][3] = __expf(sf[f][3] - nm1);
            s0 += sf[f][0] + sf[f][1];
            s1 += sf[f][2] + sf[f][3];
        }
        s0 += __shfl_xor_sync(0xffffffffu, s0, 1);
        s0 += __shfl_xor_sync(0xffffffffu, s0, 2);
        s1 += __shfl_xor_sync(0xffffffffu, s1, 1);
        s1 += __shfl_xor_sync(0xffffffffu, s1, 2);

        l0 = l0 * a0 + s0;
        l1 = l1 * a1 + s1;
        m0v = nm0; m1v = nm1;

        #pragma unroll
        for (int f = 0; f < 8; ++f) {
            of[f][0] *= a0; of[f][1] *= a0;
            of[f][2] *= a1; of[f][3] *= a1;
        }

        uint32_t pa[4][4];
        #pragma unroll
        for (int c = 0; c < 4; ++c) {
            pa[c][0] = h2_as_u32(__floats2half2_rn(sf[2*c][0],   sf[2*c][1]));
            pa[c][1] = h2_as_u32(__floats2half2_rn(sf[2*c][2],   sf[2*c][3]));
            pa[c][2] = h2_as_u32(__floats2half2_rn(sf[2*c+1][0], sf[2*c+1][1]));
            pa[c][3] = h2_as_u32(__floats2half2_rn(sf[2*c+1][2], sf[2*c+1][3]));
        }

        #pragma unroll
        for (int f = 0; f < 4; ++f) {
            #pragma unroll
            for (int kk = 0; kk < 4; ++kk) {
                uint32_t b4[4];
                const uint32_t addr = vsm +
                    ((kk * 16 + (lane & 15)) * LDAH
                     + f * 16 + ((lane >> 4) << 3)) * 2;
                ldsm_x4_t(b4, addr);
                mma16816(of[2 * f],     pa[kk], b4,     of[2 * f]);
                mma16816(of[2 * f + 1], pa[kk], b4 + 2, of[2 * f + 1]);
            }
        }
    }

    {
        const float inv0 = 1.0f / l0;
        const float inv1 = 1.0f / l1;
        const int b = bh >> 4, h = bh & 15;
        const int r0 = n0 + wid * 16 + (lane >> 2);
        const int r1 = r0 + 8;
        const size_t base0 = ((size_t)(b * SEQ_N) + r0) * E_DIM + h * D_HEAD + (lane & 3) * 2;
        const size_t base1 = ((size_t)(b * SEQ_N) + r1) * E_DIM + h * D_HEAD + (lane & 3) * 2;
        #pragma unroll
        for (int f = 0; f < 8; ++f) {
            *(__half2*)(o_g + base0 + f * 8) = __floats2half2_rn(of[f][0] * inv0, of[f][1] * inv0);
            *(__half2*)(o_g + base1 + f * 8) = __floats2half2_rn(of[f][2] * inv1, of[f][3] * inv1);
        }
    }
}

// ---------------------------------------------------------------------------
// Launch
// ---------------------------------------------------------------------------
static float* sym_addr_f(const void* symbol)
{
    void* p = nullptr;
    cudaGetSymbolAddress(&p, symbol);
    return reinterpret_cast<float*>(p);
}
static __half* sym_addr_h(const void* symbol)
{
    void* p = nullptr;
    cudaGetSymbolAddress(&p, symbol);
    return reinterpret_cast<__half*>(p);
}

extern "C" void kernel_launch(void* const* d_in, const int* in_sizes, int n_in,
                              void* d_out, int out_size)
{
    const float* x      = (const float*)d_in[0];
    const float* ln1_g  = (const float*)d_in[1];
    const float* ln1_b  = (const float*)d_in[2];
    const float* qkv_w  = (const float*)d_in[3];
    const float* qkv_b  = (const float*)d_in[4];
    const float* proj_w = (const float*)d_in[5];
    const float* proj_b = (const float*)d_in[6];
    const float* ln2_g  = (const float*)d_in[7];
    const float* ln2_b  = (const float*)d_in[8];
    const float* fc1_w  = (const float*)d_in[9];
    const float* fc1_b  = (const float*)d_in[10];
    const float* fc2_w  = (const float*)d_in[11];
    const float* fc2_b  = (const float*)d_in[12];
    float* out = (float*)d_out;

    __half* a  = sym_addr_h(g_a);
    __half* w  = sym_addr_h(g_w);
    __half* f  = sym_addr_h(g_f);
    float* x1  = sym_addr_f(g_x1);
    __half* qq = sym_addr_h(g_q);
    __half* kk = sym_addr_h(g_k);
    __half* vv = sym_addr_h(g_v);

    cudaFuncSetAttribute(gemm_fp16<0>, cudaFuncAttributeMaxDynamicSharedMemorySize, GEMM_SMEM);
    cudaFuncSetAttribute(gemm_fp16<1>, cudaFuncAttributeMaxDynamicSharedMemorySize, GEMM_SMEM);
    cudaFuncSetAttribute(gemm_fp16<2>, cudaFuncAttributeMaxDynamicSharedMemorySize, GEMM_SMEM);

    const int n_qkvw  = E_DIM * 3 * E_DIM;
    const int n_projw = E_DIM * E_DIM;
    const int n_fc1w  = E_DIM * FF_DIM;
    const int n_fc2w  = FF_DIM * E_DIM;

    // 1) h = LN1(x) -> fp16
    ln_fp16_kernel<<<T_TOK, 256>>>(x, ln1_g, ln1_b, a);

    // 2) qkv = h @ qkv_w + qkv_b -> head-major q/k/v (fused epilogue)
    wconv_kernel<<<n_qkvw / 1024, 256>>>(qkv_w, w, n_qkvw);
    gemm_fp16<0><<<dim3(3 * E_DIM / 128, T_TOK / 128), 256, GEMM_SMEM>>>(
        a, w, qkv_b, nullptr, nullptr, qq, kk, vv, 3 * E_DIM, E_DIM);

    // 3) attention (register-resident flash)
    attn_mma<<<dim3(SEQ_N / QT, 2 * H_NUM), 128>>>(qq, kk, vv, a);

    // 4) x1 = x + attn @ proj_w + proj_b (fused)
    wconv_kernel<<<n_projw / 1024, 256>>>(proj_w, w, n_projw);
    gemm_fp16<2><<<dim3(E_DIM / 128, T_TOK / 128), 256, GEMM_SMEM>>>(
        a, w, proj_b, x, x1, nullptr, nullptr, nullptr, E_DIM, E_DIM);

    // 5) h = LN2(x1) -> fp16
    ln_fp16_kernel<<<T_TOK, 256>>>(x1, ln2_g, ln2_b, a);

    // 6) ff = gelu(h @ fc1_w + fc1_b) -> fp16 (fused)
    wconv_kernel<<<n_fc1w / 1024, 256>>>(fc1_w, w, n_fc1w);
    gemm_fp16<1><<<dim3(FF_DIM / 128, T_TOK / 128), 256, GEMM_SMEM>>>(
        a, w, fc1_b, nullptr, nullptr, f, nullptr, nullptr, FF_DIM, E_DIM);

    // 7) out = x1 + ff @ fc2_w + fc2_b (fused)
    wconv_kernel<<<n_fc2w / 1024, 256>>>(fc2_w, w, n_fc2w);
    gemm_fp16<2><<<dim3(E_DIM / 128, T_TOK / 128), 256, GEMM_SMEM>>>(
        f, w, fc2_b, x1, out, nullptr, nullptr, nullptr, E_DIM, FF_DIM);
}

// round 15
// speedup vs baseline: 1.2270x; 1.0098x over previous
#include <cuda_runtime.h>
#include <cuda_fp16.h>
#include <mma.h>
#include <math.h>
#include <cstdint>

using namespace nvcuda;

// ---------------------------------------------------------------------------
// Problem constants (B=2, N=2048, E=1024, H=16, D=64, FF=4096)
// ---------------------------------------------------------------------------
#define T_TOK   4096
#define E_DIM   1024
#define H_NUM   16
#define D_HEAD  64
#define FF_DIM  4096
#define SEQ_N   2048
#define EPS_LN  1e-5f

// ---------------------------------------------------------------------------
// Scratch (__device__ globals; allocation-free rule)
// ---------------------------------------------------------------------------
__device__ __half g_a  [(size_t)T_TOK * E_DIM];
__device__ __half g_wbuf[(size_t)12582912];           // qkv|proj|fc1|fc2 fp16 weights
__device__ __half g_f  [(size_t)T_TOK * FF_DIM];
__device__ float  g_x1 [(size_t)T_TOK * E_DIM];
__device__ __half g_q  [(size_t)T_TOK * E_DIM];
__device__ __half g_k  [(size_t)T_TOK * E_DIM];
__device__ __half g_v  [(size_t)T_TOK * E_DIM];

#define WOFF_QKV  0
#define WOFF_PROJ 3145728
#define WOFF_FC1  4194304
#define WOFF_FC2  8388608

// ---------------------------------------------------------------------------
// Helpers
// ---------------------------------------------------------------------------
__device__ __forceinline__ float warp_sum(float v) {
    #pragma unroll
    for (int o = 16; o > 0; o >>= 1) v += __shfl_xor_sync(0xffffffffu, v, o);
    return v;
}
__device__ __forceinline__ uint32_t smem_u32(const void* p) {
    uint32_t a;
    asm("{ .reg .u64 t; cvta.to.shared.u64 t, %1; cvt.u32.u64 %0, t; }" : "=r"(a) : "l"(p));
    return a;
}
__device__ __forceinline__ uint32_t h2_as_u32(__half2 h) {
    union { __half2 h; uint32_t u; } cvt;
    cvt.h = h;
    return cvt.u;
}
__device__ __forceinline__ void ldsm_x4(uint32_t r[4], uint32_t addr) {
    asm volatile("ldmatrix.sync.aligned.m8n8.x4.shared.b16 {%0,%1,%2,%3}, [%4];"
                 : "=r"(r[0]), "=r"(r[1]), "=r"(r[2]), "=r"(r[3]) : "r"(addr));
}
__device__ __forceinline__ void ldsm_x4_t(uint32_t r[4], uint32_t addr) {
    asm volatile("ldmatrix.sync.aligned.m8n8.x4.trans.shared.b16 {%0,%1,%2,%3}, [%4];"
                 : "=r"(r[0]), "=r"(r[1]), "=r"(r[2]), "=r"(r[3]) : "r"(addr));
}
__device__ __forceinline__ void mma16816(float d[4], const uint32_t a[4],
                                         const uint32_t b[2], const float c[4]) {
    asm volatile(
        "mma.sync.aligned.m16n8k16.row.col.f32.f16.f16.f32 "
        "{%0,%1,%2,%3}, {%4,%5,%6,%7}, {%8,%9}, {%10,%11,%12,%13};"
        : "=f"(d[0]), "=f"(d[1]), "=f"(d[2]), "=f"(d[3])
        : "r"(a[0]), "r"(a[1]), "r"(a[2]), "r"(a[3]),
          "r"(b[0]), "r"(b[1]),
          "f"(c[0]), "f"(c[1]), "f"(c[2]), "f"(c[3]));
}
__device__ __forceinline__ void cp_async16(uint32_t dst, const void* src) {
    asm volatile("cp.async.cg.shared.global [%0], [%1], 16;" :: "r"(dst), "l"(src));
}
#define CP_COMMIT() asm volatile("cp.async.commit_group;" ::: "memory")
#define CP_WAIT2()  asm volatile("cp.async.wait_group 2;"  ::: "memory")

// ---------------------------------------------------------------------------
// LayerNorm -> fp16
// ---------------------------------------------------------------------------
__global__ void ln_fp16_kernel(const float* __restrict__ x,
                               const float* __restrict__ gamma,
                               const float* __restrict__ beta,
                               __half* __restrict__ o16)
{
    const int row = blockIdx.x;
    const int tid = threadIdx.x;
    const int w   = tid >> 5;
    const int ln  = tid & 31;

    const float4 v = reinterpret_cast<const float4*>(x + (size_t)row * E_DIM)[tid];
    float s  = v.x + v.y + v.z + v.w;
    float sq = v.x * v.x + v.y * v.y + v.z * v.z + v.w * v.w;
    s  = warp_sum(s);
    sq = warp_sum(sq);

    __shared__ float red_s[8], red_q[8];
    __shared__ float s_mu, s_rs;
    if (ln == 0) { red_s[w] = s; red_q[w] = sq; }
    __syncthreads();
    if (w == 0) {
        float ts = (ln < 8) ? red_s[ln] : 0.f;
        float tq = (ln < 8) ? red_q[ln] : 0.f;
        ts = warp_sum(ts); tq = warp_sum(tq);
        if (ln == 0) {
            float mu  = ts * (1.0f / E_DIM);
            float var = tq * (1.0f / E_DIM) - mu * mu;
            s_mu = mu; s_rs = rsqrtf(var + EPS_LN);
        }
    }
    __syncthreads();
    const float mu = s_mu, rs = s_rs;

    const float4 g = reinterpret_cast<const float4*>(gamma)[tid];
    const float4 b = reinterpret_cast<const float4*>(beta)[tid];
    __half h4[4];
    h4[0] = __float2half_rn((v.x - mu) * rs * g.x + b.x);
    h4[1] = __float2half_rn((v.y - mu) * rs * g.y + b.y);
    h4[2] = __float2half_rn((v.z - mu) * rs * g.z + b.z);
    h4[3] = __float2half_rn((v.w - mu) * rs * g.w + b.w);
    *reinterpret_cast<uint2*>(o16 + (size_t)row * E_DIM + tid * 4) = *reinterpret_cast<uint2*>(h4);
}

// ---------------------------------------------------------------------------
// fp32 -> fp16 (weights)
// ---------------------------------------------------------------------------
__global__ void wconv_kernel(const float* __restrict__ src,
                             __half* __restrict__ dst, int n)
{
    const int i = (blockIdx.x * blockDim.x + threadIdx.x) * 4;
    if (i >= n) return;
    const float4 v = *reinterpret_cast<const float4*>(src + i);
    __half h4[4];
    h4[0] = __float2half_rn(v.x); h4[1] = __float2half_rn(v.y);
    h4[2] = __float2half_rn(v.z); h4[3] = __float2half_rn(v.w);
    *reinterpret_cast<uint2*>(dst + i) = *reinterpret_cast<uint2*>(h4);
}

// ---------------------------------------------------------------------------
// fp16 GEMM (wmma m16n16k16), 128x128 block, 8 warps (64x32 warp tile),
// k-tile 32, 4-stage cp.async pipeline, FUSED epilogue via fp32 smem staging.
// ---------------------------------------------------------------------------
#define LDC 132
#define STG_A 10240
#define STG_B 8704
#define STG_SZ (STG_A + STG_B)
#define N_STAGES 4
#define GEMM_SMEM (N_STAGES * STG_SZ > 128 * LDC * 4 ? N_STAGES * STG_SZ : 128 * LDC * 4)

template <int EPI>
__global__ void __launch_bounds__(256)
gemm_fp16(const __half* __restrict__ A, const __half* __restrict__ B,
          const float* __restrict__ bias, const float* __restrict__ res,
          float* __restrict__ outf,
          __half* __restrict__ o0, __half* __restrict__ o1, __half* __restrict__ o2,
          int N, int K)
{
    extern __shared__ __align__(16) char sm[];
    float* Cs = (float*)sm;

    const int tid = threadIdx.x;
    const int wid = tid >> 5;
    const int wm  = wid & 1;
    const int wn  = wid >> 1;
    const int m0  = blockIdx.y * 128;
    const int n0  = blockIdx.x * 128;

    const int ca0 = tid * 2;
    const int ar0 = ca0 >> 2,  ac0 = (ca0 & 3) * 8;
    const int ar1 = (ca0+1) >> 2, ac1 = ((ca0+1) & 3) * 8;
    const int br0 = ca0 >> 4,  bc0 = (ca0 & 15) * 8;
    const int br1 = (ca0+1) >> 4, bc1 = ((ca0+1) & 15) * 8;

    wmma::fragment<wmma::accumulator, 16, 16, 16, float> acc[4][2];
    #pragma unroll
    for (int i = 0; i < 4; ++i)
        #pragma unroll
        for (int j = 0; j < 2; ++j) wmma::fill_fragment(acc[i][j], 0.0f);

    const int nt = K >> 5;

    auto issue = [&](int ti, int s) {
        char* st = sm + s * STG_SZ;
        const int k0 = ti * 32;
        cp_async16(smem_u32(st + (ar0 * 40 + ac0) * 2),
                   A + (size_t)(m0 + ar0) * K + k0 + ac0);
        cp_async16(smem_u32(st + (ar1 * 40 + ac1) * 2),
                   A + (size_t)(m0 + ar1) * K + k0 + ac1);
        cp_async16(smem_u32(st + STG_A + (br0 * 136 + bc0) * 2),
                   B + (size_t)(k0 + br0) * N + n0 + bc0);
        cp_async16(smem_u32(st + STG_A + (br1 * 136 + bc1) * 2),
                   B + (size_t)(k0 + br1) * N + n0 + bc1);
    };

    issue(0, 0); CP_COMMIT();
    if (nt > 1) issue(1, 1);
    CP_COMMIT();
    if (nt > 2) issue(2, 2);
    CP_COMMIT();

    int s = 0;
    for (int ti = 0; ti < nt; ++ti) {
        CP_WAIT2();
        __syncthreads();

        const __half* As = (const __half*)(sm + s * STG_SZ);
        const __half* Bs = (const __half*)(sm + s * STG_SZ + STG_A);

        #pragma unroll
        for (int kk = 0; kk < 2; ++kk) {
            wmma::fragment<wmma::matrix_a, 16, 16, 16, __half, wmma::row_major> af[4];
            wmma::fragment<wmma::matrix_b, 16, 16, 16, __half, wmma::row_major> bf[2];
            #pragma unroll
            for (int i = 0; i < 4; ++i)
                wmma::load_matrix_sync(af[i], As + (wm * 64 + i * 16) * 40 + kk * 16, 40);
            #pragma unroll
            for (int j = 0; j < 2; ++j)
                wmma::load_matrix_sync(bf[j], Bs + (kk * 16) * 136 + wn * 32 + j * 16, 136);
            #pragma unroll
            for (int i = 0; i < 4; ++i)
                #pragma unroll
                for (int j = 0; j < 2; ++j)
                    wmma::mma_sync(acc[i][j], af[i], bf[j], acc[i][j]);
        }

        if (ti + 3 < nt) issue(ti + 3, (ti + 3) & 3);
        CP_COMMIT();

        s = (s + 1) & 3;
    }
    __syncthreads();

    #pragma unroll
    for (int i = 0; i < 4; ++i)
        #pragma unroll
        for (int j = 0; j < 2; ++j)
            wmma::store_matrix_sync(Cs + (wm * 64 + i * 16) * LDC + wn * 32 + j * 16,
                                    acc[i][j], LDC, wmma::mem_row_major);
    __syncthreads();

    {
        const int r   = tid >> 1;
        const int ch  = (tid & 1) * 64;
        const int row = m0 + r;
        const int c0  = n0 + ch;
        const float* cr = Cs + r * LDC + ch;

        if (EPI == 0) {
            const int sss = c0 >> 10;
            const int hh  = (c0 & 1023) >> 6;
            const float sc = (sss == 0) ? 0.125f : 1.0f;
            const int bb = row >> 11, nn = row & 2047;
            __half* dst = ((sss == 0) ? o0 : (sss == 1) ? o1 : o2)
                        + (((size_t)(bb * H_NUM + hh)) * SEQ_N + nn) * D_HEAD;
            #pragma unroll
            for (int j = 0; j < 64; j += 8) {
                __half h8[8];
                #pragma unroll
                for (int q = 0; q < 8; ++q)
                    h8[q] = __float2half_rn((cr[j + q] + bias[c0 + j + q]) * sc);
                *reinterpret_cast<uint4*>(dst + j) = *reinterpret_cast<uint4*>(h8);
            }
        } else if (EPI == 1) {
            __half* dst = o0 + (size_t)row * N + c0;
            #pragma unroll
            for (int j = 0; j < 64; j += 8) {
                __half h8[8];
                #pragma unroll
                for (int q = 0; q < 8; ++q) {
                    const float v = cr[j + q] + bias[c0 + j + q];
                    h8[q] = __float2half_rn(0.5f * v * (1.0f + erff(v * 0.70710678118654752f)));
                }
                *reinterpret_cast<uint4*>(dst + j) = *reinterpret_cast<uint4*>(h8);
            }
        } else {
            const float* rp = res + (size_t)row * N + c0;
            float* op = outf + (size_t)row * N + c0;
            #pragma unroll
            for (int j = 0; j < 64; j += 4) {
                const float4 b4 = *reinterpret_cast<const float4*>(bias + c0 + j);
                const float4 r4 = *reinterpret_cast<const float4*>(rp + j);
                float4 o;
                o.x = cr[j + 0] + b4.x + r4.x;
                o.y = cr[j + 1] + b4.y + r4.y;
                o.z = cr[j + 2] + b4.z + r4.z;
                o.w = cr[j + 3] + b4.w + r4.w;
                *reinterpret_cast<float4*>(op + j) = o;
            }
        }
    }
}

// ---------------------------------------------------------------------------
// Flash attention, register-resident (QT=64, 128 thr; measured-best).
// ---------------------------------------------------------------------------
#define QT   64
#define KTT  64
#define LDAH 72

__global__ void __launch_bounds__(128)
attn_mma(const __half* __restrict__ q_g, const __half* __restrict__ k_g,
         const __half* __restrict__ v_g, __half* __restrict__ o_g)
{
    __shared__ __half Qs[QT * LDAH];
    __shared__ __half Ks[KTT * LDAH];
    __shared__ __half Vs[KTT * LDAH];

    const int tid  = threadIdx.x;
    const int lane = tid & 31;
    const int wid  = tid >> 5;
    const int bh   = blockIdx.y;
    const int n0   = blockIdx.x * QT;

    {
        const int4* qp = (const int4*)(q_g + ((size_t)bh * SEQ_N + n0) * D_HEAD);
        #pragma unroll
        for (int i = 0; i < 4; ++i) {
            const int idx = tid + i * 128;
            *(int4*)(Qs + (idx >> 3) * LDAH + (idx & 7) * 8) = qp[idx];
        }
    }
    __syncthreads();

    const uint32_t qsm = smem_u32(Qs);
    uint32_t qa[4][4];
    {
        const int rq = wid * 16 + (lane & 15);
        #pragma unroll
        for (int c = 0; c < 4; ++c) {
            const uint32_t addr = qsm + (rq * LDAH + c * 16 + ((lane >> 4) << 3)) * 2;
            ldsm_x4(qa[c], addr);
        }
    }

    const uint32_t ksm = smem_u32(Ks);
    const uint32_t vsm = smem_u32(Vs);

    float of[8][4];
    #pragma unroll
    for (int f = 0; f < 8; ++f)
        #pragma unroll
        for (int q = 0; q < 4; ++q) of[f][q] = 0.f;
    float m0v = -1e30f, m1v = -1e30f, l0 = 0.f, l1 = 0.f;

    for (int j0 = 0; j0 < SEQ_N; j0 += KTT) {
        __syncthreads();
        {
            const int4* kp = (const int4*)(k_g + ((size_t)bh * SEQ_N + j0) * D_HEAD);
            const int4* vp = (const int4*)(v_g + ((size_t)bh * SEQ_N + j0) * D_HEAD);
            #pragma unroll
            for (int i = 0; i < 4; ++i) {
                const int idx = tid + i * 128;
                const int off = (idx >> 3) * LDAH + (idx & 7) * 8;
                *(int4*)(Ks + off) = kp[idx];
                *(int4*)(Vs + off) = vp[idx];
            }
        }
        __syncthreads();

        float sf[8][4];
        #pragma unroll
        for (int f = 0; f < 8; ++f)
            #pragma unroll
            for (int q = 0; q < 4; ++q) sf[f][q] = 0.f;

        #pragma unroll
        for (int f = 0; f < 4; ++f) {
            #pragma unroll
            for (int kk = 0; kk < 4; ++kk) {
                uint32_t b4[4];
                const uint32_t addr = ksm +
                    ((f * 16 + (lane & 7) + ((lane >> 4) << 3)) * LDAH
                     + kk * 16 + (lane & 8)) * 2;
                ldsm_x4(b4, addr);
                mma16816(sf[2 * f],     qa[kk], b4,     sf[2 * f]);
                mma16816(sf[2 * f + 1], qa[kk], b4 + 2, sf[2 * f + 1]);
            }
        }

        float mx0 = -1e30f, mx1 = -1e30f;
        #pragma unroll
        for (int f = 0; f < 8; ++f) {
            mx0 = fmaxf(mx0, fmaxf(sf[f][0], sf[f][1]));
            mx1 = fmaxf(mx1, fmaxf(sf[f][2], sf[f][3]));
        }
        mx0 = fmaxf(mx0, __shfl_xor_sync(0xffffffffu, mx0, 1));
        mx0 = fmaxf(mx0, __shfl_xor_sync(0xffffffffu, mx0, 2));
        mx1 = fmaxf(mx1, __shfl_xor_sync(0xffffffffu, mx1, 1));
        mx1 = fmaxf(mx1, __shfl_xor_sync(0xffffffffu, mx1, 2));

        const float nm0 = fmaxf(m0v, mx0);
        const float nm1 = fmaxf(m1v, mx1);
        const float a0  = __expf(m0v - nm0);
        const float a1  = __expf(m1v - nm1);

        float s0 = 0.f, s1 = 0.f;
        #pragma unroll
        for (int f = 0; f < 8; ++f) {
            sf[f][0] = __expf(sf[f][0] - nm0);
            sf[f][1] = __expf(sf[f][1] - nm0);
            sf[f][2] = __expf(sf[f][2] - nm1);
            sf[f][3] = __expf(sf[f][3] - nm1);
            s0 += sf[f][0] + sf[f][1];
            s1 += sf[f][2] + sf[f][3];
        }
        s0 += __shfl_xor_sync(0xffffffffu, s0, 1);
        s0 += __shfl_xor_sync(0xffffffffu, s0, 2);
        s1 += __shfl_xor_sync(0xffffffffu, s1, 1);
        s1 += __shfl_xor_sync(0xffffffffu, s1, 2);

        l0 = l0 * a0 + s0;
        l1 = l1 * a1 + s1;
        m0v = nm0; m1v = nm1;

        #pragma unroll
        for (int f = 0; f < 8; ++f) {
            of[f][0] *= a0; of[f][1] *= a0;
            of[f][2] *= a1; of[f][3] *= a1;
        }

        uint32_t pa[4][4];
        #pragma unroll
        for (int c = 0; c < 4; ++c) {
            pa[c][0] = h2_as_u32(__floats2half2_rn(sf[2*c][0],   sf[2*c][1]));
            pa[c][1] = h2_as_u32(__floats2half2_rn(sf[2*c][2],   sf[2*c][3]));
            pa[c][2] = h2_as_u32(__floats2half2_rn(sf[2*c+1][0], sf[2*c+1][1]));
            pa[c][3] = h2_as_u32(__floats2half2_rn(sf[2*c+1][2], sf[2*c+1][3]));
        }

        #pragma unroll
        for (int f = 0; f < 4; ++f) {
            #pragma unroll
            for (int kk = 0; kk < 4; ++kk) {
                uint32_t b4[4];
                const uint32_t addr = vsm +
                    ((kk * 16 + (lane & 15)) * LDAH
                     + f * 16 + ((lane >> 4) << 3)) * 2;
                ldsm_x4_t(b4, addr);
                mma16816(of[2 * f],     pa[kk], b4,     of[2 * f]);
                mma16816(of[2 * f + 1], pa[kk], b4 + 2, of[2 * f + 1]);
            }
        }
    }

    {
        const float inv0 = 1.0f / l0;
        const float inv1 = 1.0f / l1;
        const int b = bh >> 4, h = bh & 15;
        const int r0 = n0 + wid * 16 + (lane >> 2);
        const int r1 = r0 + 8;
        const size_t base0 = ((size_t)(b * SEQ_N) + r0) * E_DIM + h * D_HEAD + (lane & 3) * 2;
        const size_t base1 = ((size_t)(b * SEQ_N) + r1) * E_DIM + h * D_HEAD + (lane & 3) * 2;
        #pragma unroll
        for (int f = 0; f < 8; ++f) {
            *(__half2*)(o_g + base0 + f * 8) = __floats2half2_rn(of[f][0] * inv0, of[f][1] * inv0);
            *(__half2*)(o_g + base1 + f * 8) = __floats2half2_rn(of[f][2] * inv1, of[f][3] * inv1);
        }
    }
}

// ---------------------------------------------------------------------------
// Launch (dual-stream: weight conversion overlaps the main compute chain)
// ---------------------------------------------------------------------------
static float* sym_addr_f(const void* symbol)
{
    void* p = nullptr;
    cudaGetSymbolAddress(&p, symbol);
    return reinterpret_cast<float*>(p);
}
static __half* sym_addr_h(const void* symbol)
{
    void* p = nullptr;
    cudaGetSymbolAddress(&p, symbol);
    return reinterpret_cast<__half*>(p);
}

extern "C" void kernel_launch(void* const* d_in, const int* in_sizes, int n_in,
                              void* d_out, int out_size)
{
    const float* x      = (const float*)d_in[0];
    const float* ln1_g  = (const float*)d_in[1];
    const float* ln1_b  = (const float*)d_in[2];
    const float* qkv_w  = (const float*)d_in[3];
    const float* qkv_b  = (const float*)d_in[4];
    const float* proj_w = (const float*)d_in[5];
    const float* proj_b = (const float*)d_in[6];
    const float* ln2_g  = (const float*)d_in[7];
    const float* ln2_b  = (const float*)d_in[8];
    const float* fc1_w  = (const float*)d_in[9];
    const float* fc1_b  = (const float*)d_in[10];
    const float* fc2_w  = (const float*)d_in[11];
    const float* fc2_b  = (const float*)d_in[12];
    float* out = (float*)d_out;

    __half* a    = sym_addr_h(g_a);
    __half* wbuf = sym_addr_h(g_wbuf);
    __half* f    = sym_addr_h(g_f);
    float* x1    = sym_addr_f(g_x1);
    __half* qq   = sym_addr_h(g_q);
    __half* kk   = sym_addr_h(g_k);
    __half* vv   = sym_addr_h(g_v);

    __half* w_qkv  = wbuf + WOFF_QKV;
    __half* w_proj = wbuf + WOFF_PROJ;
    __half* w_fc1  = wbuf + WOFF_FC1;
    __half* w_fc2  = wbuf + WOFF_FC2;

    // Streams/events created once on the (uncaptured) first call; reused during
    // capture. Per-call work is identical -> deterministic.
    static cudaStream_t s2 = [] {
        cudaStream_t t;
        cudaStreamCreateWithFlags(&t, cudaStreamNonBlocking);
        return t;
    }();
    static cudaEvent_t ev_fork = [] {
        cudaEvent_t e; cudaEventCreateWithFlags(&e, cudaEventDisableTiming); return e;
    }();
    static cudaEvent_t ev_qkv = [] {
        cudaEvent_t e; cudaEventCreateWithFlags(&e, cudaEventDisableTiming); return e;
    }();
    static cudaEvent_t ev_all = [] {
        cudaEvent_t e; cudaEventCreateWithFlags(&e, cudaEventDisableTiming); return e;
    }();
    static bool attrs_set = [] {
        cudaFuncSetAttribute(gemm_fp16<0>, cudaFuncAttributeMaxDynamicSharedMemorySize, GEMM_SMEM);
        cudaFuncSetAttribute(gemm_fp16<1>, cudaFuncAttributeMaxDynamicSharedMemorySize, GEMM_SMEM);
        cudaFuncSetAttribute(gemm_fp16<2>, cudaFuncAttributeMaxDynamicSharedMemorySize, GEMM_SMEM);
        return true;
    }();
    (void)attrs_set;

    const int n_qkvw  = E_DIM * 3 * E_DIM;
    const int n_projw = E_DIM * E_DIM;
    const int n_fc1w  = E_DIM * FF_DIM;
    const int n_fc2w  = FF_DIM * E_DIM;

    // ---- fork: weight conversions on s2, compute chain on default stream
    cudaEventRecord(ev_fork, 0);
    cudaStreamWaitEvent(s2, ev_fork, 0);

    wconv_kernel<<<n_qkvw / 1024, 256, 0, s2>>>(qkv_w, w_qkv, n_qkvw);
    cudaEventRecord(ev_qkv, s2);
    wconv_kernel<<<n_projw / 1024, 256, 0, s2>>>(proj_w, w_proj, n_projw);
    wconv_kernel<<<n_fc1w / 1024, 256, 0, s2>>>(fc1_w, w_fc1, n_fc1w);
    wconv_kernel<<<n_fc2w / 1024, 256, 0, s2>>>(fc2_w, w_fc2, n_fc2w);
    cudaEventRecord(ev_all, s2);

    // 1) h = LN1(x) -> fp16   (overlaps wconv on s2)
    ln_fp16_kernel<<<T_TOK, 256>>>(x, ln1_g, ln1_b, a);

    // 2) qkv GEMM (needs w_qkv)
    cudaStreamWaitEvent(0, ev_qkv, 0);
    gemm_fp16<0><<<dim3(3 * E_DIM / 128, T_TOK / 128), 256, GEMM_SMEM>>>(
        a, w_qkv, qkv_b, nullptr, nullptr, qq, kk, vv, 3 * E_DIM, E_DIM);

    // 3) attention
    attn_mma<<<dim3(SEQ_N / QT, 2 * H_NUM), 128>>>(qq, kk, vv, a);

    // remaining GEMMs need the rest of the weights (long since converted)
    cudaStreamWaitEvent(0, ev_all, 0);

    // 4) x1 = x + attn @ proj_w + proj_b
    gemm_fp16<2><<<dim3(E_DIM / 128, T_TOK / 128), 256, GEMM_SMEM>>>(
        a, w_proj, proj_b, x, x1, nullptr, nullptr, nullptr, E_DIM, E_DIM);

    // 5) h = LN2(x1) -> fp16
    ln_fp16_kernel<<<T_TOK, 256>>>(x1, ln2_g, ln2_b, a);

    // 6) ff = gelu(h @ fc1_w + fc1_b) -> fp16
    gemm_fp16<1><<<dim3(FF_DIM / 128, T_TOK / 128), 256, GEMM_SMEM>>>(
        a, w_fc1, fc1_b, nullptr, nullptr, f, nullptr, nullptr, FF_DIM, E_DIM);

    // 7) out = x1 + ff @ fc2_w + fc2_b
    gemm_fp16<2><<<dim3(E_DIM / 128, T_TOK / 128), 256, GEMM_SMEM>>>(
        f, w_fc2, fc2_b, x1, out, nullptr, nullptr, nullptr, E_DIM, FF_DIM);
}

// round 16
// speedup vs baseline: 1.2863x; 1.0483x over previous
#include <cuda_runtime.h>
#include <cuda_fp16.h>
#include <mma.h>
#include <math.h>
#include <cstdint>

using namespace nvcuda;

// ---------------------------------------------------------------------------
// Problem constants (B=2, N=2048, E=1024, H=16, D=64, FF=4096)
// ---------------------------------------------------------------------------
#define T_TOK   4096
#define E_DIM   1024
#define H_NUM   16
#define D_HEAD  64
#define FF_DIM  4096
#define SEQ_N   2048
#define EPS_LN  1e-5f

// ---------------------------------------------------------------------------
// Scratch (__device__ globals; allocation-free rule)
// ---------------------------------------------------------------------------
__device__ __half g_a  [(size_t)T_TOK * E_DIM];
__device__ __half g_wbuf[(size_t)12582912];           // qkv|proj|fc1|fc2 fp16 weights
__device__ __half g_f  [(size_t)T_TOK * FF_DIM];
__device__ float  g_x1 [(size_t)T_TOK * E_DIM];
__device__ __half g_q  [(size_t)T_TOK * E_DIM];
__device__ __half g_k  [(size_t)T_TOK * E_DIM];
__device__ __half g_v  [(size_t)T_TOK * E_DIM];

#define WOFF_QKV  0
#define WOFF_PROJ 3145728
#define WOFF_FC1  4194304
#define WOFF_FC2  8388608

// ---------------------------------------------------------------------------
// Helpers
// ---------------------------------------------------------------------------
__device__ __forceinline__ float warp_sum(float v) {
    #pragma unroll
    for (int o = 16; o > 0; o >>= 1) v += __shfl_xor_sync(0xffffffffu, v, o);
    return v;
}
__device__ __forceinline__ uint32_t smem_u32(const void* p) {
    uint32_t a;
    asm("{ .reg .u64 t; cvta.to.shared.u64 t, %1; cvt.u32.u64 %0, t; }" : "=r"(a) : "l"(p));
    return a;
}
__device__ __forceinline__ uint32_t h2_as_u32(__half2 h) {
    union { __half2 h; uint32_t u; } cvt;
    cvt.h = h;
    return cvt.u;
}
__device__ __forceinline__ void ldsm_x4(uint32_t r[4], uint32_t addr) {
    asm volatile("ldmatrix.sync.aligned.m8n8.x4.shared.b16 {%0,%1,%2,%3}, [%4];"
                 : "=r"(r[0]), "=r"(r[1]), "=r"(r[2]), "=r"(r[3]) : "r"(addr));
}
__device__ __forceinline__ void ldsm_x4_t(uint32_t r[4], uint32_t addr) {
    asm volatile("ldmatrix.sync.aligned.m8n8.x4.trans.shared.b16 {%0,%1,%2,%3}, [%4];"
                 : "=r"(r[0]), "=r"(r[1]), "=r"(r[2]), "=r"(r[3]) : "r"(addr));
}
__device__ __forceinline__ void mma16816(float d[4], const uint32_t a[4],
                                         const uint32_t b[2], const float c[4]) {
    asm volatile(
        "mma.sync.aligned.m16n8k16.row.col.f32.f16.f16.f32 "
        "{%0,%1,%2,%3}, {%4,%5,%6,%7}, {%8,%9}, {%10,%11,%12,%13};"
        : "=f"(d[0]), "=f"(d[1]), "=f"(d[2]), "=f"(d[3])
        : "r"(a[0]), "r"(a[1]), "r"(a[2]), "r"(a[3]),
          "r"(b[0]), "r"(b[1]),
          "f"(c[0]), "f"(c[1]), "f"(c[2]), "f"(c[3]));
}
__device__ __forceinline__ void cp_async16(uint32_t dst, const void* src) {
    asm volatile("cp.async.cg.shared.global [%0], [%1], 16;" :: "r"(dst), "l"(src));
}
#define CP_COMMIT() asm volatile("cp.async.commit_group;" ::: "memory")
#define CP_WAIT2()  asm volatile("cp.async.wait_group 2;"  ::: "memory")

// ---------------------------------------------------------------------------
// LayerNorm -> fp16
// ---------------------------------------------------------------------------
__global__ void ln_fp16_kernel(const float* __restrict__ x,
                               const float* __restrict__ gamma,
                               const float* __restrict__ beta,
                               __half* __restrict__ o16)
{
    const int row = blockIdx.x;
    const int tid = threadIdx.x;
    const int w   = tid >> 5;
    const int ln  = tid & 31;

    const float4 v = reinterpret_cast<const float4*>(x + (size_t)row * E_DIM)[tid];
    float s  = v.x + v.y + v.z + v.w;
    float sq = v.x * v.x + v.y * v.y + v.z * v.z + v.w * v.w;
    s  = warp_sum(s);
    sq = warp_sum(sq);

    __shared__ float red_s[8], red_q[8];
    __shared__ float s_mu, s_rs;
    if (ln == 0) { red_s[w] = s; red_q[w] = sq; }
    __syncthreads();
    if (w == 0) {
        float ts = (ln < 8) ? red_s[ln] : 0.f;
        float tq = (ln < 8) ? red_q[ln] : 0.f;
        ts = warp_sum(ts); tq = warp_sum(tq);
        if (ln == 0) {
            float mu  = ts * (1.0f / E_DIM);
            float var = tq * (1.0f / E_DIM) - mu * mu;
            s_mu = mu; s_rs = rsqrtf(var + EPS_LN);
        }
    }
    __syncthreads();
    const float mu = s_mu, rs = s_rs;

    const float4 g = reinterpret_cast<const float4*>(gamma)[tid];
    const float4 b = reinterpret_cast<const float4*>(beta)[tid];
    __half h4[4];
    h4[0] = __float2half_rn((v.x - mu) * rs * g.x + b.x);
    h4[1] = __float2half_rn((v.y - mu) * rs * g.y + b.y);
    h4[2] = __float2half_rn((v.z - mu) * rs * g.z + b.z);
    h4[3] = __float2half_rn((v.w - mu) * rs * g.w + b.w);
    *reinterpret_cast<uint2*>(o16 + (size_t)row * E_DIM + tid * 4) = *reinterpret_cast<uint2*>(h4);
}

// ---------------------------------------------------------------------------
// fp32 -> fp16 (weights)
// ---------------------------------------------------------------------------
__global__ void wconv_kernel(const float* __restrict__ src,
                             __half* __restrict__ dst, int n)
{
    const int i = (blockIdx.x * blockDim.x + threadIdx.x) * 4;
    if (i >= n) return;
    const float4 v = *reinterpret_cast<const float4*>(src + i);
    __half h4[4];
    h4[0] = __float2half_rn(v.x); h4[1] = __float2half_rn(v.y);
    h4[2] = __float2half_rn(v.z); h4[3] = __float2half_rn(v.w);
    *reinterpret_cast<uint2*>(dst + i) = *reinterpret_cast<uint2*>(h4);
}

// ---------------------------------------------------------------------------
// fp16 GEMM (wmma m16n16k16), 128x128 block, 8 warps (64x32 warp tile),
// k-tile 32, 4-stage cp.async pipeline, FUSED epilogue via fp32 smem staging.
// Operates on a per-batch row range via offset pointers (rows 0..2047).
// ---------------------------------------------------------------------------
#define LDC 132
#define STG_A 10240
#define STG_B 8704
#define STG_SZ (STG_A + STG_B)
#define N_STAGES 4
#define GEMM_SMEM (N_STAGES * STG_SZ > 128 * LDC * 4 ? N_STAGES * STG_SZ : 128 * LDC * 4)

template <int EPI>
__global__ void __launch_bounds__(256)
gemm_fp16(const __half* __restrict__ A, const __half* __restrict__ B,
          const float* __restrict__ bias, const float* __restrict__ res,
          float* __restrict__ outf,
          __half* __restrict__ o0, __half* __restrict__ o1, __half* __restrict__ o2,
          int N, int K)
{
    extern __shared__ __align__(16) char sm[];
    float* Cs = (float*)sm;

    const int tid = threadIdx.x;
    const int wid = tid >> 5;
    const int wm  = wid & 1;
    const int wn  = wid >> 1;
    const int m0  = blockIdx.y * 128;
    const int n0  = blockIdx.x * 128;

    const int ca0 = tid * 2;
    const int ar0 = ca0 >> 2,  ac0 = (ca0 & 3) * 8;
    const int ar1 = (ca0+1) >> 2, ac1 = ((ca0+1) & 3) * 8;
    const int br0 = ca0 >> 4,  bc0 = (ca0 & 15) * 8;
    const int br1 = (ca0+1) >> 4, bc1 = ((ca0+1) & 15) * 8;

    wmma::fragment<wmma::accumulator, 16, 16, 16, float> acc[4][2];
    #pragma unroll
    for (int i = 0; i < 4; ++i)
        #pragma unroll
        for (int j = 0; j < 2; ++j) wmma::fill_fragment(acc[i][j], 0.0f);

    const int nt = K >> 5;

    auto issue = [&](int ti, int s) {
        char* st = sm + s * STG_SZ;
        const int k0 = ti * 32;
        cp_async16(smem_u32(st + (ar0 * 40 + ac0) * 2),
                   A + (size_t)(m0 + ar0) * K + k0 + ac0);
        cp_async16(smem_u32(st + (ar1 * 40 + ac1) * 2),
                   A + (size_t)(m0 + ar1) * K + k0 + ac1);
        cp_async16(smem_u32(st + STG_A + (br0 * 136 + bc0) * 2),
                   B + (size_t)(k0 + br0) * N + n0 + bc0);
        cp_async16(smem_u32(st + STG_A + (br1 * 136 + bc1) * 2),
                   B + (size_t)(k0 + br1) * N + n0 + bc1);
    };

    issue(0, 0); CP_COMMIT();
    if (nt > 1) issue(1, 1);
    CP_COMMIT();
    if (nt > 2) issue(2, 2);
    CP_COMMIT();

    int s = 0;
    for (int ti = 0; ti < nt; ++ti) {
        CP_WAIT2();
        __syncthreads();

        const __half* As = (const __half*)(sm + s * STG_SZ);
        const __half* Bs = (const __half*)(sm + s * STG_SZ + STG_A);

        #pragma unroll
        for (int kk = 0; kk < 2; ++kk) {
            wmma::fragment<wmma::matrix_a, 16, 16, 16, __half, wmma::row_major> af[4];
            wmma::fragment<wmma::matrix_b, 16, 16, 16, __half, wmma::row_major> bf[2];
            #pragma unroll
            for (int i = 0; i < 4; ++i)
                wmma::load_matrix_sync(af[i], As + (wm * 64 + i * 16) * 40 + kk * 16, 40);
            #pragma unroll
            for (int j = 0; j < 2; ++j)
                wmma::load_matrix_sync(bf[j], Bs + (kk * 16) * 136 + wn * 32 + j * 16, 136);
            #pragma unroll
            for (int i = 0; i < 4; ++i)
                #pragma unroll
                for (int j = 0; j < 2; ++j)
                    wmma::mma_sync(acc[i][j], af[i], bf[j], acc[i][j]);
        }

        if (ti + 3 < nt) issue(ti + 3, (ti + 3) & 3);
        CP_COMMIT();

        s = (s + 1) & 3;
    }
    __syncthreads();

    #pragma unroll
    for (int i = 0; i < 4; ++i)
        #pragma unroll
        for (int j = 0; j < 2; ++j)
            wmma::store_matrix_sync(Cs + (wm * 64 + i * 16) * LDC + wn * 32 + j * 16,
                                    acc[i][j], LDC, wmma::mem_row_major);
    __syncthreads();

    {
        const int r   = tid >> 1;
        const int ch  = (tid & 1) * 64;
        const int row = m0 + r;                  // row within this batch half
        const int c0  = n0 + ch;
        const float* cr = Cs + r * LDC + ch;

        if (EPI == 0) {
            const int sss = c0 >> 10;
            const int hh  = (c0 & 1023) >> 6;
            const float sc = (sss == 0) ? 0.125f : 1.0f;
            __half* dst = ((sss == 0) ? o0 : (sss == 1) ? o1 : o2)
                        + ((size_t)hh * SEQ_N + row) * D_HEAD;
            #pragma unroll
            for (int j = 0; j < 64; j += 8) {
                __half h8[8];
                #pragma unroll
                for (int q = 0; q < 8; ++q)
                    h8[q] = __float2half_rn((cr[j + q] + bias[c0 + j + q]) * sc);
                *reinterpret_cast<uint4*>(dst + j) = *reinterpret_cast<uint4*>(h8);
            }
        } else if (EPI == 1) {
            __half* dst = o0 + (size_t)row * N + c0;
            #pragma unroll
            for (int j = 0; j < 64; j += 8) {
                __half h8[8];
                #pragma unroll
                for (int q = 0; q < 8; ++q) {
                    const float v = cr[j + q] + bias[c0 + j + q];
                    h8[q] = __float2half_rn(0.5f * v * (1.0f + erff(v * 0.70710678118654752f)));
                }
                *reinterpret_cast<uint4*>(dst + j) = *reinterpret_cast<uint4*>(h8);
            }
        } else {
            const float* rp = res + (size_t)row * N + c0;
            float* op = outf + (size_t)row * N + c0;
            #pragma unroll
            for (int j = 0; j < 64; j += 4) {
                const float4 b4 = *reinterpret_cast<const float4*>(bias + c0 + j);
                const float4 r4 = *reinterpret_cast<const float4*>(rp + j);
                float4 o;
                o.x = cr[j + 0] + b4.x + r4.x;
                o.y = cr[j + 1] + b4.y + r4.y;
                o.z = cr[j + 2] + b4.z + r4.z;
                o.w = cr[j + 3] + b4.w + r4.w;
                *reinterpret_cast<float4*>(op + j) = o;
            }
        }
    }
}

// ---------------------------------------------------------------------------
// Flash attention, register-resident (QT=64, 128 thr; measured-best).
// Per-batch launch: grid.y = H_NUM heads; pointers pre-offset to the batch.
// ---------------------------------------------------------------------------
#define QT   64
#define KTT  64
#define LDAH 72

__global__ void __launch_bounds__(128)
attn_mma(const __half* __restrict__ q_g, const __half* __restrict__ k_g,
         const __half* __restrict__ v_g, __half* __restrict__ o_g)
{
    __shared__ __half Qs[QT * LDAH];
    __shared__ __half Ks[KTT * LDAH];
    __shared__ __half Vs[KTT * LDAH];

    const int tid  = threadIdx.x;
    const int lane = tid & 31;
    const int wid  = tid >> 5;
    const int h    = blockIdx.y;            // head within this batch
    const int n0   = blockIdx.x * QT;

    {
        const int4* qp = (const int4*)(q_g + ((size_t)h * SEQ_N + n0) * D_HEAD);
        #pragma unroll
        for (int i = 0; i < 4; ++i) {
            const int idx = tid + i * 128;
            *(int4*)(Qs + (idx >> 3) * LDAH + (idx & 7) * 8) = qp[idx];
        }
    }
    __syncthreads();

    const uint32_t qsm = smem_u32(Qs);
    uint32_t qa[4][4];
    {
        const int rq = wid * 16 + (lane & 15);
        #pragma unroll
        for (int c = 0; c < 4; ++c) {
            const uint32_t addr = qsm + (rq * LDAH + c * 16 + ((lane >> 4) << 3)) * 2;
            ldsm_x4(qa[c], addr);
        }
    }

    const uint32_t ksm = smem_u32(Ks);
    const uint32_t vsm = smem_u32(Vs);

    float of[8][4];
    #pragma unroll
    for (int f = 0; f < 8; ++f)
        #pragma unroll
        for (int q = 0; q < 4; ++q) of[f][q] = 0.f;
    float m0v = -1e30f, m1v = -1e30f, l0 = 0.f, l1 = 0.f;

    for (int j0 = 0; j0 < SEQ_N; j0 += KTT) {
        __syncthreads();
        {
            const int4* kp = (const int4*)(k_g + ((size_t)h * SEQ_N + j0) * D_HEAD);
            const int4* vp = (const int4*)(v_g + ((size_t)h * SEQ_N + j0) * D_HEAD);
            #pragma unroll
            for (int i = 0; i < 4; ++i) {
                const int idx = tid + i * 128;
                const int off = (idx >> 3) * LDAH + (idx & 7) * 8;
                *(int4*)(Ks + off) = kp[idx];
                *(int4*)(Vs + off) = vp[idx];
            }
        }
        __syncthreads();

        float sf[8][4];
        #pragma unroll
        for (int f = 0; f < 8; ++f)
            #pragma unroll
            for (int q = 0; q < 4; ++q) sf[f][q] = 0.f;

        #pragma unroll
        for (int f = 0; f < 4; ++f) {
            #pragma unroll
            for (int kk = 0; kk < 4; ++kk) {
                uint32_t b4[4];
                const uint32_t addr = ksm +
                    ((f * 16 + (lane & 7) + ((lane >> 4) << 3)) * LDAH
                     + kk * 16 + (lane & 8)) * 2;
                ldsm_x4(b4, addr);
                mma16816(sf[2 * f],     qa[kk], b4,     sf[2 * f]);
                mma16816(sf[2 * f + 1], qa[kk], b4 + 2, sf[2 * f + 1]);
            }
        }

        float mx0 = -1e30f, mx1 = -1e30f;
        #pragma unroll
        for (int f = 0; f < 8; ++f) {
            mx0 = fmaxf(mx0, fmaxf(sf[f][0], sf[f][1]));
            mx1 = fmaxf(mx1, fmaxf(sf[f][2], sf[f][3]));
        }
        mx0 = fmaxf(mx0, __shfl_xor_sync(0xffffffffu, mx0, 1));
        mx0 = fmaxf(mx0, __shfl_xor_sync(0xffffffffu, mx0, 2));
        mx1 = fmaxf(mx1, __shfl_xor_sync(0xffffffffu, mx1, 1));
        mx1 = fmaxf(mx1, __shfl_xor_sync(0xffffffffu, mx1, 2));

        const float nm0 = fmaxf(m0v, mx0);
        const float nm1 = fmaxf(m1v, mx1);
        const float a0  = __expf(m0v - nm0);
        const float a1  = __expf(m1v - nm1);

        float s0 = 0.f, s1 = 0.f;
        #pragma unroll
        for (int f = 0; f < 8; ++f) {
            sf[f][0] = __expf(sf[f][0] - nm0);
            sf[f][1] = __expf(sf[f][1] - nm0);
            sf[f][2] = __expf(sf[f][2] - nm1);
            sf[f][3] = __expf(sf[f][3] - nm1);
            s0 += sf[f][0] + sf[f][1];
            s1 += sf[f][2] + sf[f][3];
        }
        s0 += __shfl_xor_sync(0xffffffffu, s0, 1);
        s0 += __shfl_xor_sync(0xffffffffu, s0, 2);
        s1 += __shfl_xor_sync(0xffffffffu, s1, 1);
        s1 += __shfl_xor_sync(0xffffffffu, s1, 2);

        l0 = l0 * a0 + s0;
        l1 = l1 * a1 + s1;
        m0v = nm0; m1v = nm1;

        #pragma unroll
        for (int f = 0; f < 8; ++f) {
            of[f][0] *= a0; of[f][1] *= a0;
            of[f][2] *= a1; of[f][3] *= a1;
        }

        uint32_t pa[4][4];
        #pragma unroll
        for (int c = 0; c < 4; ++c) {
            pa[c][0] = h2_as_u32(__floats2half2_rn(sf[2*c][0],   sf[2*c][1]));
            pa[c][1] = h2_as_u32(__floats2half2_rn(sf[2*c][2],   sf[2*c][3]));
            pa[c][2] = h2_as_u32(__floats2half2_rn(sf[2*c+1][0], sf[2*c+1][1]));
            pa[c][3] = h2_as_u32(__floats2half2_rn(sf[2*c+1][2], sf[2*c+1][3]));
        }

        #pragma unroll
        for (int f = 0; f < 4; ++f) {
            #pragma unroll
            for (int kk = 0; kk < 4; ++kk) {
                uint32_t b4[4];
                const uint32_t addr = vsm +
                    ((kk * 16 + (lane & 15)) * LDAH
                     + f * 16 + ((lane >> 4) << 3)) * 2;
                ldsm_x4_t(b4, addr);
                mma16816(of[2 * f],     pa[kk], b4,     of[2 * f]);
                mma16816(of[2 * f + 1], pa[kk], b4 + 2, of[2 * f + 1]);
            }
        }
    }

    {
        const float inv0 = 1.0f / l0;
        const float inv1 = 1.0f / l1;
        const int r0 = n0 + wid * 16 + (lane >> 2);
        const int r1 = r0 + 8;
        const size_t base0 = (size_t)r0 * E_DIM + h * D_HEAD + (lane & 3) * 2;
        const size_t base1 = (size_t)r1 * E_DIM + h * D_HEAD + (lane & 3) * 2;
        #pragma unroll
        for (int f = 0; f < 8; ++f) {
            *(__half2*)(o_g + base0 + f * 8) = __floats2half2_rn(of[f][0] * inv0, of[f][1] * inv0);
            *(__half2*)(o_g + base1 + f * 8) = __floats2half2_rn(of[f][2] * inv1, of[f][3] * inv1);
        }
    }
}

// ---------------------------------------------------------------------------
// Launch: two independent per-batch chains on two streams + wconv stream
// ---------------------------------------------------------------------------
static float* sym_addr_f(const void* symbol)
{
    void* p = nullptr;
    cudaGetSymbolAddress(&p, symbol);
    return reinterpret_cast<float*>(p);
}
static __half* sym_addr_h(const void* symbol)
{
    void* p = nullptr;
    cudaGetSymbolAddress(&p, symbol);
    return reinterpret_cast<__half*>(p);
}

extern "C" void kernel_launch(void* const* d_in, const int* in_sizes, int n_in,
                              void* d_out, int out_size)
{
    const float* x      = (const float*)d_in[0];
    const float* ln1_g  = (const float*)d_in[1];
    const float* ln1_b  = (const float*)d_in[2];
    const float* qkv_w  = (const float*)d_in[3];
    const float* qkv_b  = (const float*)d_in[4];
    const float* proj_w = (const float*)d_in[5];
    const float* proj_b = (const float*)d_in[6];
    const float* ln2_g  = (const float*)d_in[7];
    const float* ln2_b  = (const float*)d_in[8];
    const float* fc1_w  = (const float*)d_in[9];
    const float* fc1_b  = (const float*)d_in[10];
    const float* fc2_w  = (const float*)d_in[11];
    const float* fc2_b  = (const float*)d_in[12];
    float* out = (float*)d_out;

    __half* a    = sym_addr_h(g_a);
    __half* wbuf = sym_addr_h(g_wbuf);
    __half* f    = sym_addr_h(g_f);
    float* x1    = sym_addr_f(g_x1);
    __half* qq   = sym_addr_h(g_q);
    __half* kk   = sym_addr_h(g_k);
    __half* vv   = sym_addr_h(g_v);

    __half* w_qkv  = wbuf + WOFF_QKV;
    __half* w_proj = wbuf + WOFF_PROJ;
    __half* w_fc1  = wbuf + WOFF_FC1;
    __half* w_fc2  = wbuf + WOFF_FC2;

    static cudaStream_t s2 = [] {
        cudaStream_t t; cudaStreamCreateWithFlags(&t, cudaStreamNonBlocking); return t;
    }();
    static cudaStream_t s3 = [] {
        cudaStream_t t; cudaStreamCreateWithFlags(&t, cudaStreamNonBlocking); return t;
    }();
    static cudaEvent_t ev_fork = [] {
        cudaEvent_t e; cudaEventCreateWithFlags(&e, cudaEventDisableTiming); return e;
    }();
    static cudaEvent_t ev_wqkv = [] {
        cudaEvent_t e; cudaEventCreateWithFlags(&e, cudaEventDisableTiming); return e;
    }();
    static cudaEvent_t ev_wall = [] {
        cudaEvent_t e; cudaEventCreateWithFlags(&e, cudaEventDisableTiming); return e;
    }();
    static cudaEvent_t ev_b1 = [] {
        cudaEvent_t e; cudaEventCreateWithFlags(&e, cudaEventDisableTiming); return e;
    }();
    static bool attrs_set = [] {
        cudaFuncSetAttribute(gemm_fp16<0>, cudaFuncAttributeMaxDynamicSharedMemorySize, GEMM_SMEM);
        cudaFuncSetAttribute(gemm_fp16<1>, cudaFuncAttributeMaxDynamicSharedMemorySize, GEMM_SMEM);
        cudaFuncSetAttribute(gemm_fp16<2>, cudaFuncAttributeMaxDynamicSharedMemorySize, GEMM_SMEM);
        return true;
    }();
    (void)attrs_set;

    const int n_qkvw  = E_DIM * 3 * E_DIM;
    const int n_projw = E_DIM * E_DIM;
    const int n_fc1w  = E_DIM * FF_DIM;
    const int n_fc2w  = FF_DIM * E_DIM;

    // ---- fork: weight conversions on s3
    cudaEventRecord(ev_fork, 0);
    cudaStreamWaitEvent(s3, ev_fork, 0);
    cudaStreamWaitEvent(s2, ev_fork, 0);

    wconv_kernel<<<n_qkvw / 1024, 256, 0, s3>>>(qkv_w, w_qkv, n_qkvw);
    cudaEventRecord(ev_wqkv, s3);
    wconv_kernel<<<n_projw / 1024, 256, 0, s3>>>(proj_w, w_proj, n_projw);
    wconv_kernel<<<n_fc1w / 1024, 256, 0, s3>>>(fc1_w, w_fc1, n_fc1w);
    wconv_kernel<<<n_fc2w / 1024, 256, 0, s3>>>(fc2_w, w_fc2, n_fc2w);
    cudaEventRecord(ev_wall, s3);

    // ---- two independent per-batch chains
    const size_t HB = (size_t)SEQ_N * E_DIM;      // elements per batch half (tok-major)
    const size_t FB = (size_t)SEQ_N * FF_DIM;

    for (int b = 0; b < 2; ++b) {
        cudaStream_t st = (b == 0) ? (cudaStream_t)0 : s2;
        const float* xb  = x   + b * HB;
        __half* ab       = a   + b * HB;
        __half* qb       = qq  + b * HB;           // head-major offset == HB
        __half* kb       = kk  + b * HB;
        __half* vb       = vv  + b * HB;
        float*  x1b      = x1  + b * HB;
        __half* fb       = f   + b * FB;
        float*  outb     = out + b * HB;

        // 1) LN1
        ln_fp16_kernel<<<SEQ_N, 256, 0, st>>>(xb, ln1_g, ln1_b, ab);

        // 2) qkv GEMM (needs w_qkv)
        cudaStreamWaitEvent(st, ev_wqkv, 0);
        gemm_fp16<0><<<dim3(3 * E_DIM / 128, SEQ_N / 128), 256, GEMM_SMEM, st>>>(
            ab, w_qkv, qkv_b, nullptr, nullptr, qb, kb, vb, 3 * E_DIM, E_DIM);

        // 3) attention
        attn_mma<<<dim3(SEQ_N / QT, H_NUM), 128, 0, st>>>(qb, kb, vb, ab);

        // 4) proj (+x residual) — needs remaining weights
        cudaStreamWaitEvent(st, ev_wall, 0);
        gemm_fp16<2><<<dim3(E_DIM / 128, SEQ_N / 128), 256, GEMM_SMEM, st>>>(
            ab, w_proj, proj_b, xb, x1b, nullptr, nullptr, nullptr, E_DIM, E_DIM);

        // 5) LN2
        ln_fp16_kernel<<<SEQ_N, 256, 0, st>>>(x1b, ln2_g, ln2_b, ab);

        // 6) fc1 + gelu
        gemm_fp16<1><<<dim3(FF_DIM / 128, SEQ_N / 128), 256, GEMM_SMEM, st>>>(
            ab, w_fc1, fc1_b, nullptr, nullptr, fb, nullptr, nullptr, FF_DIM, E_DIM);

        // 7) fc2 (+x1 residual) -> out
        gemm_fp16<2><<<dim3(E_DIM / 128, SEQ_N / 128), 256, GEMM_SMEM, st>>>(
            fb, w_fc2, fc2_b, x1b, outb, nullptr, nullptr, nullptr, E_DIM, FF_DIM);
    }

    // ---- join: batch-1 chain must complete before kernel_launch's stream ends
    cudaEventRecord(ev_b1, s2);
    cudaStreamWaitEvent(0, ev_b1, 0);
}